// round 8
// baseline (speedup 1.0000x reference)
#include <cuda_runtime.h>
#include <cuda_bf16.h>
#include <cstdint>

// EdgeDecoder: out[e] = sigmoid( relu([src_e ; dst_e] @ W1 + b1) @ W2 + b2 )
// Round 8: TILE_E=128, 8 MMA warps (64x32 tiles) + 4 gather warps,
// quarter-K cp.async ping-pong, prepass bf16 hi/lo node tables.

#define D        128
#define K2       256
#define TILE_E   128
#define NTHREADS 384            // warps 0..7 MMA, 8..11 gather
#define GRID     148
#define N_NODES_MAX 100000

// SMEM layout (bytes)
#define OFF_WHI  0              // W^T hi [128 n][264 k] bf16, stride 528B
#define OFF_WLO  67584
#define OFF_X0   135168         // chunk buf: 128 rows x (hi 128B | lo 128B), stride 272B
#define OFF_X1   169984
#define OFF_B1   204800
#define OFF_W2   205312
#define OFF_HP   205824         // f32[128][4]
#define SMEM_TOTAL 207872

__device__ __align__(16) __nv_bfloat16 g_src_bf[(size_t)N_NODES_MAX * 256];
__device__ __align__(16) __nv_bfloat16 g_dst_bf[(size_t)N_NODES_MAX * 256];

__device__ __forceinline__ uint32_t smem_u32(const void* p) {
    uint32_t a;
    asm("{ .reg .u64 t; cvta.to.shared.u64 t, %1; cvt.u32.u64 %0, t; }" : "=r"(a) : "l"(p));
    return a;
}
__device__ __forceinline__ void cp16(uint32_t saddr, const void* gaddr) {
    asm volatile("cp.async.cg.shared.global [%0], [%1], 16;" :: "r"(saddr), "l"(gaddr));
}
#define CP_COMMIT() asm volatile("cp.async.commit_group;" ::: "memory")
#define CP_WAIT1()  asm volatile("cp.async.wait_group 1;" ::: "memory")

__device__ __forceinline__ void ldsm_x4(uint32_t* r, uint32_t addr) {
    asm volatile("ldmatrix.sync.aligned.m8n8.x4.shared.b16 {%0,%1,%2,%3}, [%4];"
                 : "=r"(r[0]), "=r"(r[1]), "=r"(r[2]), "=r"(r[3]) : "r"(addr));
}
__device__ __forceinline__ void mma16816(float c[4], const uint32_t a[4],
                                         uint32_t b0, uint32_t b1) {
    asm volatile(
        "mma.sync.aligned.m16n8k16.row.col.f32.bf16.bf16.f32 "
        "{%0,%1,%2,%3}, {%4,%5,%6,%7}, {%8,%9}, {%0,%1,%2,%3};\n"
        : "+f"(c[0]), "+f"(c[1]), "+f"(c[2]), "+f"(c[3])
        : "r"(a[0]), "r"(a[1]), "r"(a[2]), "r"(a[3]), "r"(b0), "r"(b1));
}

// ---------------- prepass: fp32 tables -> bf16 hi/lo tables ----------------
__global__ void convert_tables(const float* __restrict__ src,
                               const float* __restrict__ dst, int n_nodes)
{
    const int per_tab = n_nodes * 32;
    for (int v = blockIdx.x * blockDim.x + threadIdx.x; v < 2 * per_tab;
         v += gridDim.x * blockDim.x) {
        const float4* tab = (const float4*)(v < per_tab ? src : dst);
        __nv_bfloat16* ot = (v < per_tab) ? g_src_bf : g_dst_bf;
        int u = (v < per_tab) ? v : v - per_tab;
        int node = u >> 5, q = u & 31;
        float4 x = tab[u];
        __nv_bfloat16 hx = __float2bfloat16(x.x), hy = __float2bfloat16(x.y);
        __nv_bfloat16 hz = __float2bfloat16(x.z), hw = __float2bfloat16(x.w);
        __nv_bfloat162* oh = (__nv_bfloat162*)(ot + (size_t)node * 256 + q * 4);
        __nv_bfloat162* ol = (__nv_bfloat162*)(ot + (size_t)node * 256 + 128 + q * 4);
        oh[0] = __nv_bfloat162(hx, hy);
        oh[1] = __nv_bfloat162(hz, hw);
        ol[0] = __nv_bfloat162(__float2bfloat16(x.x - __bfloat162float(hx)),
                               __float2bfloat16(x.y - __bfloat162float(hy)));
        ol[1] = __nv_bfloat162(__float2bfloat16(x.z - __bfloat162float(hz)),
                               __float2bfloat16(x.w - __bfloat162float(hw)));
    }
}

// ---------------- main kernel ----------------
__global__ __launch_bounds__(NTHREADS, 1)
void edge_decoder_tc(const int* __restrict__ eidx,
                     const float* __restrict__ W1,
                     const float* __restrict__ b1,
                     const float* __restrict__ W2,
                     const float* __restrict__ b2,
                     float* __restrict__ out,
                     int n_edges, int n_tiles)
{
    extern __shared__ char smem[];
    const uint32_t sb = smem_u32(smem);
    const int tid  = threadIdx.x;
    const int lane = tid & 31;
    const int warp = tid >> 5;

    float* b1s   = (float*)(smem + OFF_B1);
    float* w2s   = (float*)(smem + OFF_W2);
    float* Hpart = (float*)(smem + OFF_HP);

    // gather: warps 8..11, one thread per edge row
    // chunk c: 0,1 = src (k 0-63, 64-127); 2,3 = dst
    auto issue_chunk = [&](int t, int c) {
        if (t < n_tiles) {
            int row = tid - 256;              // 0..127
            int e = t * TILE_E + row;
            int idx = (e < n_edges) ? eidx[(c >= 2 ? n_edges : 0) + e] : 0;
            const char* g = (const char*)(c >= 2 ? g_dst_bf : g_src_bf)
                          + (size_t)idx * 512 + (size_t)(c & 1) * 128;
            uint32_t d = sb + ((c & 1) ? OFF_X1 : OFF_X0) + (uint32_t)row * 272;
            #pragma unroll
            for (int i = 0; i < 8; ++i) {
                cp16(d + i * 16,       g + i * 16);         // hi 128B
                cp16(d + 128 + i * 16, g + 256 + i * 16);   // lo 128B
            }
        }
        CP_COMMIT();
    };

    int tile = blockIdx.x;
    if (warp >= 8) issue_chunk(tile, 0);      // prologue

    // one-time: W1 -> transposed bf16 hi/lo (stride 528B); b1/W2
    {
        __nv_bfloat16* wh = (__nv_bfloat16*)(smem + OFF_WHI);
        __nv_bfloat16* wl = (__nv_bfloat16*)(smem + OFF_WLO);
        for (int i = tid; i < K2 * D; i += NTHREADS) {
            int k = i >> 7;
            int n = i & 127;
            float w = W1[i];
            __nv_bfloat16 h = __float2bfloat16(w);
            wh[n * 264 + k] = h;
            wl[n * 264 + k] = __float2bfloat16(w - __bfloat162float(h));
        }
        if (tid < 128) { b1s[tid] = b1[tid]; w2s[tid] = W2[tid]; }
    }
    const float b2v = b2[0];
    __syncthreads();

    // MMA geometry: warps 0..7 = 2 warp-rows (64 edges) x 4 warp-cols (32 cols)
    const int wr = warp >> 2;                 // 0..1
    const int wc = warp & 3;                  // 0..3
    const int quad = lane >> 3, qr = lane & 7;
    const uint32_t aOff = (uint32_t)((wr * 64 + (quad & 1) * 8 + qr) * 272
                                     + (quad >> 1) * 16);
    const uint32_t bRowOff = (uint32_t)((wc * 32 + (quad >> 1) * 8 + qr) * 528
                                        + (quad & 1) * 16);
    const uint32_t bHiBase = sb + OFF_WHI + bRowOff;
    const uint32_t bLoBase = sb + OFF_WLO + bRowOff;

    for (; tile < n_tiles; tile += gridDim.x) {
        float c[4][4][4];
        #pragma unroll
        for (int mt = 0; mt < 4; ++mt)
            #pragma unroll
            for (int nt = 0; nt < 4; ++nt)
                #pragma unroll
                for (int r = 0; r < 4; ++r) c[mt][nt][r] = 0.f;

        #pragma unroll
        for (int ck = 0; ck < 4; ++ck) {
            if (warp >= 8) {
                if (ck < 3) issue_chunk(tile, ck + 1);
                else        issue_chunk(tile + gridDim.x, 0);
                CP_WAIT1();                   // chunk ck complete
            }
            __syncthreads();                  // data visible to MMA warps

            if (warp < 8) {
                const uint32_t aBase = sb + ((ck & 1) ? OFF_X1 : OFF_X0) + aOff;
                #pragma unroll
                for (int ks = 0; ks < 4; ++ks) {
                    const uint32_t koA = (uint32_t)ks * 32;
                    const uint32_t koB = (uint32_t)ck * 128 + koA;
                    uint32_t bh[8], bl[8];
                    ldsm_x4(bh,     bHiBase + koB);
                    ldsm_x4(bh + 4, bHiBase + 8448 + koB);
                    ldsm_x4(bl,     bLoBase + koB);
                    ldsm_x4(bl + 4, bLoBase + 8448 + koB);
                    #pragma unroll
                    for (int mt = 0; mt < 4; ++mt) {
                        uint32_t ah[4], al[4];
                        ldsm_x4(ah, aBase + (uint32_t)mt * (16 * 272) + koA);
                        ldsm_x4(al, aBase + (uint32_t)mt * (16 * 272) + 128 + koA);
                        #pragma unroll
                        for (int nt = 0; nt < 4; ++nt) {
                            uint32_t b0h = bh[(nt >> 1) * 4 + (nt & 1) * 2];
                            uint32_t b1h = bh[(nt >> 1) * 4 + (nt & 1) * 2 + 1];
                            uint32_t b0l = bl[(nt >> 1) * 4 + (nt & 1) * 2];
                            uint32_t b1l = bl[(nt >> 1) * 4 + (nt & 1) * 2 + 1];
                            mma16816(c[mt][nt], ah, b0h, b1h);
                            mma16816(c[mt][nt], ah, b0l, b1l);
                            mma16816(c[mt][nt], al, b0h, b1h);
                        }
                    }
                }
            }
            __syncthreads();                  // buffer (ck&1) free for reuse
        }

        // ---- epilogue: relu + W2 dot over this warp's 32 cols ----
        if (warp < 8) {
            const int tq = lane >> 2;         // 0..7
            const int tk = lane & 3;          // 0..3
            float p[8];
            #pragma unroll
            for (int mt = 0; mt < 4; ++mt) {
                float s0 = 0.f, s1 = 0.f;
                #pragma unroll
                for (int nt = 0; nt < 4; ++nt) {
                    int col = wc * 32 + nt * 8 + tk * 2;
                    float ba = b1s[col], bb = b1s[col + 1];
                    float wa = w2s[col], wb = w2s[col + 1];
                    float h;
                    h = c[mt][nt][0] + ba; h = h > 0.f ? h : 0.f; s0 = fmaf(h, wa, s0);
                    h = c[mt][nt][1] + bb; h = h > 0.f ? h : 0.f; s0 = fmaf(h, wb, s0);
                    h = c[mt][nt][2] + ba; h = h > 0.f ? h : 0.f; s1 = fmaf(h, wa, s1);
                    h = c[mt][nt][3] + bb; h = h > 0.f ? h : 0.f; s1 = fmaf(h, wb, s1);
                }
                p[mt * 2]     = s0;
                p[mt * 2 + 1] = s1;
            }
            #pragma unroll
            for (int i = 0; i < 8; ++i) {
                p[i] += __shfl_xor_sync(0xffffffffu, p[i], 1);
                p[i] += __shfl_xor_sync(0xffffffffu, p[i], 2);
            }
            if (tk == 0) {
                int rb = wr * 64;
                #pragma unroll
                for (int mt = 0; mt < 4; ++mt) {
                    Hpart[(rb + mt * 16 + tq)     * 4 + wc] = p[mt * 2];
                    Hpart[(rb + mt * 16 + tq + 8) * 4 + wc] = p[mt * 2 + 1];
                }
            }
        }
        __syncthreads();

        if (tid < TILE_E) {
            int e = tile * TILE_E + tid;
            if (e < n_edges) {
                const float* hp = Hpart + tid * 4;
                float s = (hp[0] + hp[1]) + (hp[2] + hp[3]) + b2v;
                out[e] = 1.f / (1.f + expf(-s));
            }
        }
        __syncthreads();
    }
}

extern "C" void kernel_launch(void* const* d_in, const int* in_sizes, int n_in,
                              void* d_out, int out_size)
{
    const float* src = (const float*)d_in[0];
    const float* dst = (const float*)d_in[1];
    const int*   ei  = (const int*)d_in[2];
    const float* W1  = (const float*)d_in[3];
    const float* b1  = (const float*)d_in[4];
    const float* W2  = (const float*)d_in[5];
    const float* b2  = (const float*)d_in[6];
    float*       out = (float*)d_out;

    const int n_nodes = in_sizes[0] / D;
    const int n_edges = in_sizes[2] / 2;
    const int n_tiles = (n_edges + TILE_E - 1) / TILE_E;

    convert_tables<<<1480, 256>>>(src, dst, n_nodes);

    cudaFuncSetAttribute(edge_decoder_tc,
                         cudaFuncAttributeMaxDynamicSharedMemorySize, SMEM_TOTAL);
    int grid = GRID < n_tiles ? GRID : n_tiles;
    edge_decoder_tc<<<grid, NTHREADS, SMEM_TOTAL>>>(
        ei, W1, b1, W2, b2, out, n_edges, n_tiles);
}

// round 9
// speedup vs baseline: 1.1302x; 1.1302x over previous
#include <cuda_runtime.h>
#include <cuda_bf16.h>
#include <cstdint>

// EdgeDecoder: out[e] = sigmoid( relu([src_e ; dst_e] @ W1 + b1) @ W2 + b2 )
// Round 9: R7 base (TILE_E=64, K=128 halves, 8 MMA warps 32x32 tiles) with full
// producer/consumer warp split: warps 8-15 own gather/cp.async/store; warps 0-7
// only LDSM+HMMA. 3 syncs per tile (was 6). Prepass bf16 hi/lo node tables.

#define D        128
#define K2       256
#define TILE_E   64
#define NTHREADS 512
#define GRID     148
#define N_NODES_MAX 100000

// SMEM layout (bytes)
#define OFF_WHI  0                    // W^T hi [128 n][264 k] bf16 (stride 528B)
#define OFF_WLO  67584
#define OFF_X0   135168               // half-buf: hi 64x272B | lo 64x272B
#define XBUF_SZ  34816
#define OFF_X1   (OFF_X0 + XBUF_SZ)
#define OFF_B1   (OFF_X1 + XBUF_SZ)
#define OFF_W2   (OFF_B1 + 512)
#define OFF_HP   (OFF_W2 + 512)      // f32[64][4]
#define SMEM_TOTAL (OFF_HP + 1024)

__device__ __align__(16) __nv_bfloat16 g_src_bf[(size_t)N_NODES_MAX * 256];
__device__ __align__(16) __nv_bfloat16 g_dst_bf[(size_t)N_NODES_MAX * 256];

__device__ __forceinline__ uint32_t smem_u32(const void* p) {
    uint32_t a;
    asm("{ .reg .u64 t; cvta.to.shared.u64 t, %1; cvt.u32.u64 %0, t; }" : "=r"(a) : "l"(p));
    return a;
}
__device__ __forceinline__ void cp16(uint32_t saddr, const void* gaddr) {
    asm volatile("cp.async.cg.shared.global [%0], [%1], 16;" :: "r"(saddr), "l"(gaddr));
}
#define CP_COMMIT() asm volatile("cp.async.commit_group;" ::: "memory")
#define CP_WAIT1()  asm volatile("cp.async.wait_group 1;" ::: "memory")
#define CP_WAIT0()  asm volatile("cp.async.wait_group 0;" ::: "memory")

__device__ __forceinline__ void ldsm_x4(uint32_t* r, uint32_t addr) {
    asm volatile("ldmatrix.sync.aligned.m8n8.x4.shared.b16 {%0,%1,%2,%3}, [%4];"
                 : "=r"(r[0]), "=r"(r[1]), "=r"(r[2]), "=r"(r[3]) : "r"(addr));
}
__device__ __forceinline__ void mma16816(float c[4], const uint32_t a[4],
                                         uint32_t b0, uint32_t b1) {
    asm volatile(
        "mma.sync.aligned.m16n8k16.row.col.f32.bf16.bf16.f32 "
        "{%0,%1,%2,%3}, {%4,%5,%6,%7}, {%8,%9}, {%0,%1,%2,%3};\n"
        : "+f"(c[0]), "+f"(c[1]), "+f"(c[2]), "+f"(c[3])
        : "r"(a[0]), "r"(a[1]), "r"(a[2]), "r"(a[3]), "r"(b0), "r"(b1));
}

// ---------------- prepass: fp32 tables -> bf16 hi/lo tables ----------------
__global__ void convert_tables(const float* __restrict__ src,
                               const float* __restrict__ dst, int n_nodes)
{
    const int per_tab = n_nodes * 32;
    for (int v = blockIdx.x * blockDim.x + threadIdx.x; v < 2 * per_tab;
         v += gridDim.x * blockDim.x) {
        const float4* tab = (const float4*)(v < per_tab ? src : dst);
        __nv_bfloat16* ot = (v < per_tab) ? g_src_bf : g_dst_bf;
        int u = (v < per_tab) ? v : v - per_tab;
        int node = u >> 5, q = u & 31;
        float4 x = tab[u];
        __nv_bfloat16 hx = __float2bfloat16(x.x), hy = __float2bfloat16(x.y);
        __nv_bfloat16 hz = __float2bfloat16(x.z), hw = __float2bfloat16(x.w);
        __nv_bfloat162* oh = (__nv_bfloat162*)(ot + (size_t)node * 256 + q * 4);
        __nv_bfloat162* ol = (__nv_bfloat162*)(ot + (size_t)node * 256 + 128 + q * 4);
        oh[0] = __nv_bfloat162(hx, hy);
        oh[1] = __nv_bfloat162(hz, hw);
        ol[0] = __nv_bfloat162(__float2bfloat16(x.x - __bfloat162float(hx)),
                               __float2bfloat16(x.y - __bfloat162float(hy)));
        ol[1] = __nv_bfloat162(__float2bfloat16(x.z - __bfloat162float(hz)),
                               __float2bfloat16(x.w - __bfloat162float(hw)));
    }
}

// ---------------- main kernel ----------------
__global__ __launch_bounds__(NTHREADS, 1)
void edge_decoder_tc(const int* __restrict__ eidx,
                     const float* __restrict__ W1,
                     const float* __restrict__ b1,
                     const float* __restrict__ W2,
                     const float* __restrict__ b2,
                     float* __restrict__ out,
                     int n_edges, int n_tiles)
{
    extern __shared__ char smem[];
    const uint32_t sb = smem_u32(smem);
    const int tid  = threadIdx.x;
    const int lane = tid & 31;
    const int warp = tid >> 5;

    float* b1s   = (float*)(smem + OFF_B1);
    float* w2s   = (float*)(smem + OFF_W2);
    float* Hpart = (float*)(smem + OFF_HP);

    // ---- producer side (warps 8..15): 4 threads per edge row ----
    const int gt  = tid - 256;            // 0..255 for producers
    const int grow = gt >> 2;             // 0..63
    const int gc   = gt & 3;              // 0..3 (64B slice each of hi and lo)

    auto issue_half = [&](int t, int half, int hb) {
        if (t < n_tiles) {
            int e = t * TILE_E + grow;
            int idx = (e < n_edges) ? eidx[(half ? n_edges : 0) + e] : 0;
            const char* g = (const char*)(half ? g_dst_bf : g_src_bf) + (size_t)idx * 512;
            uint32_t dhi = sb + (hb ? OFF_X1 : OFF_X0) + (uint32_t)grow * 272;
            uint32_t dlo = dhi + 64u * 272;
            #pragma unroll
            for (int i = 0; i < 4; ++i) {
                cp16(dhi + (gc * 4 + i) * 16, g + (gc * 4 + i) * 16);
                cp16(dlo + (gc * 4 + i) * 16, g + 256 + (gc * 4 + i) * 16);
            }
        }
        CP_COMMIT();
    };

    int tile = blockIdx.x;
    if (warp >= 8) issue_half(tile, 0, 0);      // prologue: half0 of first tile

    // ---- one-time: W1 -> transposed bf16 hi/lo (stride 528B); b1/W2 ----
    {
        __nv_bfloat16* wh = (__nv_bfloat16*)(smem + OFF_WHI);
        __nv_bfloat16* wl = (__nv_bfloat16*)(smem + OFF_WLO);
        for (int i = tid; i < K2 * D; i += NTHREADS) {
            int k = i >> 7;
            int n = i & 127;
            float w = W1[i];
            __nv_bfloat16 h = __float2bfloat16(w);
            wh[n * 264 + k] = h;
            wl[n * 264 + k] = __float2bfloat16(w - __bfloat162float(h));
        }
        if (tid < 128) { b1s[tid] = b1[tid]; w2s[tid] = W2[tid]; }
    }
    const float b2v = b2[0];

    // ---- consumer geometry (warps 0..7): 2 warp-rows x 4 warp-cols, 32x32 ----
    const int wr = (warp >> 2) & 1;
    const int wc = warp & 3;
    const int quad = lane >> 3, qr = lane & 7;
    const uint32_t aOff = (uint32_t)((wr * 32 + (quad & 1) * 8 + qr) * 272
                                     + (quad >> 1) * 16);
    const uint32_t bRowOff = (uint32_t)((wc * 32 + (quad >> 1) * 8 + qr) * 528
                                        + (quad & 1) * 16);
    const uint32_t bHiBase = sb + OFF_WHI + bRowOff;
    const uint32_t bLoBase = sb + OFF_WLO + bRowOff;

    __syncthreads();   // W staged; producers' prologue issued

    for (; tile < n_tiles; tile += gridDim.x) {
        float c[2][4][4];
        #pragma unroll
        for (int mt = 0; mt < 2; ++mt)
            #pragma unroll
            for (int nt = 0; nt < 4; ++nt)
                #pragma unroll
                for (int r = 0; r < 4; ++r) c[mt][nt][r] = 0.f;

        // MMA over one K=128 half from buffer hb
        auto mma_half = [&](int h) {
            const uint32_t aHi = sb + (h ? OFF_X1 : OFF_X0) + aOff;
            const uint32_t aLo = aHi + 64u * 272;
            const uint32_t bK  = (uint32_t)h * 256;
            #pragma unroll 4
            for (int ks = 0; ks < 8; ++ks) {
                const uint32_t ko = (uint32_t)ks * 32;
                uint32_t ah[8], al[8], bh[8], bl[8];
                ldsm_x4(ah,     aHi + ko);
                ldsm_x4(ah + 4, aHi + 4352 + ko);
                ldsm_x4(al,     aLo + ko);
                ldsm_x4(al + 4, aLo + 4352 + ko);
                ldsm_x4(bh,     bHiBase + bK + ko);
                ldsm_x4(bh + 4, bHiBase + 8448 + bK + ko);
                ldsm_x4(bl,     bLoBase + bK + ko);
                ldsm_x4(bl + 4, bLoBase + 8448 + bK + ko);
                #pragma unroll
                for (int mt = 0; mt < 2; ++mt) {
                    #pragma unroll
                    for (int nt = 0; nt < 4; ++nt) {
                        uint32_t b0h = bh[(nt >> 1) * 4 + (nt & 1) * 2];
                        uint32_t b1h = bh[(nt >> 1) * 4 + (nt & 1) * 2 + 1];
                        uint32_t b0l = bl[(nt >> 1) * 4 + (nt & 1) * 2];
                        uint32_t b1l = bl[(nt >> 1) * 4 + (nt & 1) * 2 + 1];
                        mma16816(c[mt][nt], ah + mt * 4, b0h, b1h);
                        mma16816(c[mt][nt], ah + mt * 4, b0l, b1l);
                        mma16816(c[mt][nt], al + mt * 4, b0h, b1h);
                    }
                }
            }
        };

        if (warp >= 8) {
            issue_half(tile, 1, 1);   // dst half into buf1
            CP_WAIT1();               // half0 (buf0) complete
        }
        __syncthreads();              // A: buf0 ready

        if (warp < 8) mma_half(0);
        else          CP_WAIT0();     // half1 (buf1) complete

        __syncthreads();              // C: buf1 ready AND buf0 reads done

        if (warp >= 8) issue_half(tile + gridDim.x, 0, 0);  // prefetch next tile
        if (warp < 8) {
            mma_half(1);

            // ---- epilogue: relu + W2 dot over this warp's 32 cols ----
            const int tq = lane >> 2;
            const int tk = lane & 3;
            float p[4];
            #pragma unroll
            for (int mt = 0; mt < 2; ++mt) {
                float s0 = 0.f, s1 = 0.f;
                #pragma unroll
                for (int nt = 0; nt < 4; ++nt) {
                    int col = wc * 32 + nt * 8 + tk * 2;
                    float ba = b1s[col], bb = b1s[col + 1];
                    float wa = w2s[col], wb = w2s[col + 1];
                    float h;
                    h = c[mt][nt][0] + ba; h = h > 0.f ? h : 0.f; s0 = fmaf(h, wa, s0);
                    h = c[mt][nt][1] + bb; h = h > 0.f ? h : 0.f; s0 = fmaf(h, wb, s0);
                    h = c[mt][nt][2] + ba; h = h > 0.f ? h : 0.f; s1 = fmaf(h, wa, s1);
                    h = c[mt][nt][3] + bb; h = h > 0.f ? h : 0.f; s1 = fmaf(h, wb, s1);
                }
                p[mt * 2]     = s0;
                p[mt * 2 + 1] = s1;
            }
            #pragma unroll
            for (int i = 0; i < 4; ++i) {
                p[i] += __shfl_xor_sync(0xffffffffu, p[i], 1);
                p[i] += __shfl_xor_sync(0xffffffffu, p[i], 2);
            }
            if (tk == 0) {
                int rb = wr * 32;
                Hpart[(rb + tq)      * 4 + wc] = p[0];
                Hpart[(rb + tq + 8)  * 4 + wc] = p[1];
                Hpart[(rb + tq + 16) * 4 + wc] = p[2];
                Hpart[(rb + tq + 24) * 4 + wc] = p[3];
            }
        }
        __syncthreads();              // E: Hpart ready; buf1 reads done

        // producers finalize output while consumers roll into next tile
        if (warp >= 8 && gt < TILE_E) {
            int e = tile * TILE_E + gt;
            if (e < n_edges) {
                const float* hp = Hpart + gt * 4;
                float s = (hp[0] + hp[1]) + (hp[2] + hp[3]) + b2v;
                out[e] = 1.f / (1.f + expf(-s));
            }
        }
    }
}

extern "C" void kernel_launch(void* const* d_in, const int* in_sizes, int n_in,
                              void* d_out, int out_size)
{
    const float* src = (const float*)d_in[0];
    const float* dst = (const float*)d_in[1];
    const int*   ei  = (const int*)d_in[2];
    const float* W1  = (const float*)d_in[3];
    const float* b1  = (const float*)d_in[4];
    const float* W2  = (const float*)d_in[5];
    const float* b2  = (const float*)d_in[6];
    float*       out = (float*)d_out;

    const int n_nodes = in_sizes[0] / D;
    const int n_edges = in_sizes[2] / 2;
    const int n_tiles = (n_edges + TILE_E - 1) / TILE_E;

    convert_tables<<<1480, 256>>>(src, dst, n_nodes);

    cudaFuncSetAttribute(edge_decoder_tc,
                         cudaFuncAttributeMaxDynamicSharedMemorySize, SMEM_TOTAL);
    int grid = GRID < n_tiles ? GRID : n_tiles;
    edge_decoder_tc<<<grid, NTHREADS, SMEM_TOTAL>>>(
        ei, W1, b1, W2, b2, out, n_edges, n_tiles);
}

// round 10
// speedup vs baseline: 1.3395x; 1.1853x over previous
#include <cuda_runtime.h>
#include <cuda_fp16.h>
#include <cstdint>

// EdgeDecoder: out[e] = sigmoid( relu([src_e ; dst_e] @ W1 + b1) @ W2 + b2 )
// Round 10: fp16 2-pass split (X = hi+lo fp16, W single fp16), TILE_E=128,
// 16 MMA warps (32x32 tiles), K-half double-buffered cp.async, k-stagger.

#define D        128
#define K2       256
#define TILE_E   128
#define NTHREADS 512
#define GRID     148
#define N_NODES_MAX 100000

// SMEM layout (bytes)
#define OFF_W    0                    // W^T fp16 [128 n][264 k] (stride 528B) = 67584
#define OFF_X0   67584                // half-buf: hi 128x272B | lo 128x272B = 69632
#define XH_SZ    34816
#define XBUF_SZ  69632
#define OFF_X1   (OFF_X0 + XBUF_SZ)   // 137216
#define OFF_B1   (OFF_X1 + XBUF_SZ)   // 206848
#define OFF_W2   (OFF_B1 + 512)
#define OFF_HP   (OFF_W2 + 512)       // f32[128][4]
#define SMEM_TOTAL (OFF_HP + 2048)    // 209920

// Pre-converted node tables: [node][hi 128 fp16 | lo 128 fp16] = 512B/node
__device__ __align__(16) __half g_src_h[(size_t)N_NODES_MAX * 256];
__device__ __align__(16) __half g_dst_h[(size_t)N_NODES_MAX * 256];

__device__ __forceinline__ uint32_t smem_u32(const void* p) {
    uint32_t a;
    asm("{ .reg .u64 t; cvta.to.shared.u64 t, %1; cvt.u32.u64 %0, t; }" : "=r"(a) : "l"(p));
    return a;
}
__device__ __forceinline__ void cp16(uint32_t saddr, const void* gaddr) {
    asm volatile("cp.async.cg.shared.global [%0], [%1], 16;" :: "r"(saddr), "l"(gaddr));
}
#define CP_COMMIT() asm volatile("cp.async.commit_group;" ::: "memory")
#define CP_WAIT1()  asm volatile("cp.async.wait_group 1;" ::: "memory")

__device__ __forceinline__ void ldsm_x4(uint32_t* r, uint32_t addr) {
    asm volatile("ldmatrix.sync.aligned.m8n8.x4.shared.b16 {%0,%1,%2,%3}, [%4];"
                 : "=r"(r[0]), "=r"(r[1]), "=r"(r[2]), "=r"(r[3]) : "r"(addr));
}
__device__ __forceinline__ void mma16816(float c[4], const uint32_t a[4],
                                         uint32_t b0, uint32_t b1) {
    asm volatile(
        "mma.sync.aligned.m16n8k16.row.col.f32.f16.f16.f32 "
        "{%0,%1,%2,%3}, {%4,%5,%6,%7}, {%8,%9}, {%0,%1,%2,%3};\n"
        : "+f"(c[0]), "+f"(c[1]), "+f"(c[2]), "+f"(c[3])
        : "r"(a[0]), "r"(a[1]), "r"(a[2]), "r"(a[3]), "r"(b0), "r"(b1));
}

// ---------------- prepass: fp32 tables -> fp16 hi/lo tables ----------------
__global__ void convert_tables(const float* __restrict__ src,
                               const float* __restrict__ dst, int n_nodes)
{
    const int per_tab = n_nodes * 32;
    for (int v = blockIdx.x * blockDim.x + threadIdx.x; v < 2 * per_tab;
         v += gridDim.x * blockDim.x) {
        const float4* tab = (const float4*)(v < per_tab ? src : dst);
        __half* ot = (v < per_tab) ? g_src_h : g_dst_h;
        int u = (v < per_tab) ? v : v - per_tab;
        int node = u >> 5, q = u & 31;
        float4 x = tab[u];
        __half hx = __float2half_rn(x.x), hy = __float2half_rn(x.y);
        __half hz = __float2half_rn(x.z), hw = __float2half_rn(x.w);
        __half2* oh = (__half2*)(ot + (size_t)node * 256 + q * 4);
        __half2* ol = (__half2*)(ot + (size_t)node * 256 + 128 + q * 4);
        oh[0] = __halves2half2(hx, hy);
        oh[1] = __halves2half2(hz, hw);
        ol[0] = __halves2half2(__float2half_rn(x.x - __half2float(hx)),
                               __float2half_rn(x.y - __half2float(hy)));
        ol[1] = __halves2half2(__float2half_rn(x.z - __half2float(hz)),
                               __float2half_rn(x.w - __half2float(hw)));
    }
}

// ---------------- main kernel ----------------
__global__ __launch_bounds__(NTHREADS, 1)
void edge_decoder_tc(const int* __restrict__ eidx,
                     const float* __restrict__ W1,
                     const float* __restrict__ b1,
                     const float* __restrict__ W2,
                     const float* __restrict__ b2,
                     float* __restrict__ out,
                     int n_edges, int n_tiles)
{
    extern __shared__ char smem[];
    const uint32_t sb = smem_u32(smem);
    const int tid  = threadIdx.x;
    const int lane = tid & 31;
    const int warp = tid >> 5;

    float* b1s   = (float*)(smem + OFF_B1);
    float* w2s   = (float*)(smem + OFF_W2);
    float* Hpart = (float*)(smem + OFF_HP);

    // ---- gather: 4 threads per edge row, all warps ----
    const int grow = tid >> 2;            // 0..127
    const int gc   = tid & 3;             // 64B slice each of hi and lo

    auto issue_half = [&](int t, int half, int hb) {
        if (t < n_tiles) {
            int e = t * TILE_E + grow;
            int idx = (e < n_edges) ? eidx[(half ? n_edges : 0) + e] : 0;
            const char* g = (const char*)(half ? g_dst_h : g_src_h) + (size_t)idx * 512;
            uint32_t dhi = sb + (hb ? OFF_X1 : OFF_X0) + (uint32_t)grow * 272;
            uint32_t dlo = dhi + XH_SZ;
            #pragma unroll
            for (int i = 0; i < 4; ++i) {
                cp16(dhi + (gc * 4 + i) * 16, g + (gc * 4 + i) * 16);
                cp16(dlo + (gc * 4 + i) * 16, g + 256 + (gc * 4 + i) * 16);
            }
        }
        CP_COMMIT();
    };

    int tile = blockIdx.x;
    issue_half(tile, 0, 0);               // prologue: src half of first tile

    // ---- one-time: W1 -> transposed fp16 (stride 528B); b1/W2 ----
    {
        __half* w = (__half*)(smem + OFF_W);
        for (int i = tid; i < K2 * D; i += NTHREADS) {
            int k = i >> 7;
            int n = i & 127;
            w[n * 264 + k] = __float2half_rn(W1[i]);
        }
        if (tid < 128) { b1s[tid] = b1[tid]; w2s[tid] = W2[tid]; }
    }
    const float b2v = b2[0];

    // ---- MMA geometry: 16 warps = 4 warp-rows (32 edges) x 4 warp-cols (32 cols)
    const int wr = warp >> 2;             // 0..3
    const int wc = warp & 3;              // 0..3
    const int quad = lane >> 3, qr = lane & 7;
    const uint32_t aOff = (uint32_t)((wr * 32 + (quad & 1) * 8 + qr) * 272
                                     + (quad >> 1) * 16);
    const uint32_t bBase = sb + OFF_W
        + (uint32_t)((wc * 32 + (quad >> 1) * 8 + qr) * 528 + (quad & 1) * 16);
    const int krev = warp & 1;            // odd warps iterate k in reverse

    __syncthreads();

    for (; tile < n_tiles; tile += gridDim.x) {
        float c[2][4][4];
        #pragma unroll
        for (int mt = 0; mt < 2; ++mt)
            #pragma unroll
            for (int nt = 0; nt < 4; ++nt)
                #pragma unroll
                for (int r = 0; r < 4; ++r) c[mt][nt][r] = 0.f;

        auto mma_half = [&](int h, int hb) {
            const uint32_t aHi = sb + (hb ? OFF_X1 : OFF_X0) + aOff;
            const uint32_t aLo = aHi + XH_SZ;
            const uint32_t bK  = (uint32_t)h * 256;
            #pragma unroll 4
            for (int ks = 0; ks < 8; ++ks) {
                const int kss = krev ? (7 - ks) : ks;       // stagger
                const uint32_t ko = (uint32_t)kss * 32;
                uint32_t ah[8], al[8], bh[8];
                ldsm_x4(ah,     aHi + ko);
                ldsm_x4(ah + 4, aHi + 4352 + ko);
                ldsm_x4(al,     aLo + ko);
                ldsm_x4(al + 4, aLo + 4352 + ko);
                ldsm_x4(bh,     bBase + bK + ko);
                ldsm_x4(bh + 4, bBase + 8448 + bK + ko);
                #pragma unroll
                for (int mt = 0; mt < 2; ++mt) {
                    #pragma unroll
                    for (int nt = 0; nt < 4; ++nt) {
                        uint32_t b0 = bh[(nt >> 1) * 4 + (nt & 1) * 2];
                        uint32_t b1r = bh[(nt >> 1) * 4 + (nt & 1) * 2 + 1];
                        mma16816(c[mt][nt], ah + mt * 4, b0, b1r);
                        mma16816(c[mt][nt], al + mt * 4, b0, b1r);
                    }
                }
            }
        };

        issue_half(tile, 1, 1);           // dst half into buf1
        CP_WAIT1();                       // buf0 (src) complete
        __syncthreads();

        mma_half(0, 0);
        __syncthreads();                  // buf0 reads done

        issue_half(tile + gridDim.x, 0, 0);   // prefetch next tile's src
        CP_WAIT1();                       // buf1 (dst) complete
        __syncthreads();

        mma_half(1, 1);

        // ---- epilogue: relu + W2 dot over this warp's 32 cols ----
        {
            const int tq = lane >> 2;
            const int tk = lane & 3;
            float p[4];
            #pragma unroll
            for (int mt = 0; mt < 2; ++mt) {
                float s0 = 0.f, s1 = 0.f;
                #pragma unroll
                for (int nt = 0; nt < 4; ++nt) {
                    int col = wc * 32 + nt * 8 + tk * 2;
                    float ba = b1s[col], bb = b1s[col + 1];
                    float wa = w2s[col], wb = w2s[col + 1];
                    float h;
                    h = c[mt][nt][0] + ba; h = h > 0.f ? h : 0.f; s0 = fmaf(h, wa, s0);
                    h = c[mt][nt][1] + bb; h = h > 0.f ? h : 0.f; s0 = fmaf(h, wb, s0);
                    h = c[mt][nt][2] + ba; h = h > 0.f ? h : 0.f; s1 = fmaf(h, wa, s1);
                    h = c[mt][nt][3] + bb; h = h > 0.f ? h : 0.f; s1 = fmaf(h, wb, s1);
                }
                p[mt * 2]     = s0;
                p[mt * 2 + 1] = s1;
            }
            #pragma unroll
            for (int i = 0; i < 4; ++i) {
                p[i] += __shfl_xor_sync(0xffffffffu, p[i], 1);
                p[i] += __shfl_xor_sync(0xffffffffu, p[i], 2);
            }
            if (tk == 0) {
                int rb = wr * 32;
                Hpart[(rb + tq)      * 4 + wc] = p[0];
                Hpart[(rb + tq + 8)  * 4 + wc] = p[1];
                Hpart[(rb + tq + 16) * 4 + wc] = p[2];
                Hpart[(rb + tq + 24) * 4 + wc] = p[3];
            }
        }
        __syncthreads();                  // Hpart ready; buf1 reads done

        if (tid < TILE_E) {
            int e = tile * TILE_E + tid;
            if (e < n_edges) {
                const float* hp = Hpart + tid * 4;
                float s = (hp[0] + hp[1]) + (hp[2] + hp[3]) + b2v;
                out[e] = 1.f / (1.f + expf(-s));
            }
        }
        // no extra barrier: next Hpart write is after two more barriers
    }
}

extern "C" void kernel_launch(void* const* d_in, const int* in_sizes, int n_in,
                              void* d_out, int out_size)
{
    const float* src = (const float*)d_in[0];
    const float* dst = (const float*)d_in[1];
    const int*   ei  = (const int*)d_in[2];
    const float* W1  = (const float*)d_in[3];
    const float* b1  = (const float*)d_in[4];
    const float* W2  = (const float*)d_in[5];
    const float* b2  = (const float*)d_in[6];
    float*       out = (float*)d_out;

    const int n_nodes = in_sizes[0] / D;
    const int n_edges = in_sizes[2] / 2;
    const int n_tiles = (n_edges + TILE_E - 1) / TILE_E;

    convert_tables<<<1480, 256>>>(src, dst, n_nodes);

    cudaFuncSetAttribute(edge_decoder_tc,
                         cudaFuncAttributeMaxDynamicSharedMemorySize, SMEM_TOTAL);
    int grid = GRID < n_tiles ? GRID : n_tiles;
    edge_decoder_tc<<<grid, NTHREADS, SMEM_TOTAL>>>(
        ei, W1, b1, W2, b2, out, n_edges, n_tiles);
}

// round 11
// speedup vs baseline: 1.5857x; 1.1838x over previous
#include <cuda_runtime.h>
#include <cuda_fp16.h>
#include <cstdint>

// EdgeDecoder: out[e] = sigmoid( relu([src_e ; dst_e] @ W1 + b1) @ W2 + b2 )
// Round 11: fp16 2-pass split; CTA = 4 independent 4-warp pipelines, each with
// private 32-edge chunks, private double-buffered X tiles, named group barriers.

#define D        128
#define K2       256
#define CHUNK_E  32                  // edges per group-chunk
#define NTHREADS 512
#define GRID     148
#define N_NODES_MAX 100000

// SMEM layout (bytes)
#define OFF_W     0                  // W^T fp16 [128 n][264 k] (stride 528B) = 67584
#define OFF_X     67584              // 4 groups x 2 bufs x (hi 32x272 | lo 32x272)
#define XH_SZ     8704               // 32 rows * 272B
#define XBUF_SZ   17408              // hi + lo
#define XGRP_SZ   34816              // 2 buffers
#define OFF_B1    (OFF_X + 4 * XGRP_SZ)   // 206848
#define OFF_W2    (OFF_B1 + 512)
#define OFF_HP    (OFF_W2 + 512)     // 4 groups x f32[32][4] = 2048
#define SMEM_TOTAL (OFF_HP + 2048)   // 209920

// Pre-converted node tables: [node][hi 128 fp16 | lo 128 fp16] = 512B/node
__device__ __align__(16) __half g_src_h[(size_t)N_NODES_MAX * 256];
__device__ __align__(16) __half g_dst_h[(size_t)N_NODES_MAX * 256];

__device__ __forceinline__ uint32_t smem_u32(const void* p) {
    uint32_t a;
    asm("{ .reg .u64 t; cvta.to.shared.u64 t, %1; cvt.u32.u64 %0, t; }" : "=r"(a) : "l"(p));
    return a;
}
__device__ __forceinline__ void cp16(uint32_t saddr, const void* gaddr) {
    asm volatile("cp.async.cg.shared.global [%0], [%1], 16;" :: "r"(saddr), "l"(gaddr));
}
#define CP_COMMIT() asm volatile("cp.async.commit_group;" ::: "memory")
#define CP_WAIT1()  asm volatile("cp.async.wait_group 1;" ::: "memory")

__device__ __forceinline__ void ldsm_x4(uint32_t* r, uint32_t addr) {
    asm volatile("ldmatrix.sync.aligned.m8n8.x4.shared.b16 {%0,%1,%2,%3}, [%4];"
                 : "=r"(r[0]), "=r"(r[1]), "=r"(r[2]), "=r"(r[3]) : "r"(addr));
}
__device__ __forceinline__ void mma16816(float c[4], const uint32_t a[4],
                                         uint32_t b0, uint32_t b1) {
    asm volatile(
        "mma.sync.aligned.m16n8k16.row.col.f32.f16.f16.f32 "
        "{%0,%1,%2,%3}, {%4,%5,%6,%7}, {%8,%9}, {%0,%1,%2,%3};\n"
        : "+f"(c[0]), "+f"(c[1]), "+f"(c[2]), "+f"(c[3])
        : "r"(a[0]), "r"(a[1]), "r"(a[2]), "r"(a[3]), "r"(b0), "r"(b1));
}

// ---------------- prepass: fp32 tables -> fp16 hi/lo tables ----------------
__global__ void convert_tables(const float* __restrict__ src,
                               const float* __restrict__ dst, int n_nodes)
{
    const int per_tab = n_nodes * 32;
    for (int v = blockIdx.x * blockDim.x + threadIdx.x; v < 2 * per_tab;
         v += gridDim.x * blockDim.x) {
        const float4* tab = (const float4*)(v < per_tab ? src : dst);
        __half* ot = (v < per_tab) ? g_src_h : g_dst_h;
        int u = (v < per_tab) ? v : v - per_tab;
        int node = u >> 5, q = u & 31;
        float4 x = tab[u];
        __half hx = __float2half_rn(x.x), hy = __float2half_rn(x.y);
        __half hz = __float2half_rn(x.z), hw = __float2half_rn(x.w);
        __half2* oh = (__half2*)(ot + (size_t)node * 256 + q * 4);
        __half2* ol = (__half2*)(ot + (size_t)node * 256 + 128 + q * 4);
        oh[0] = __halves2half2(hx, hy);
        oh[1] = __halves2half2(hz, hw);
        ol[0] = __halves2half2(__float2half_rn(x.x - __half2float(hx)),
                               __float2half_rn(x.y - __half2float(hy)));
        ol[1] = __halves2half2(__float2half_rn(x.z - __half2float(hz)),
                               __float2half_rn(x.w - __half2float(hw)));
    }
}

// ---------------- main kernel ----------------
__global__ __launch_bounds__(NTHREADS, 1)
void edge_decoder_tc(const int* __restrict__ eidx,
                     const float* __restrict__ W1,
                     const float* __restrict__ b1,
                     const float* __restrict__ W2,
                     const float* __restrict__ b2,
                     float* __restrict__ out,
                     int n_edges, int n_chunks)
{
    extern __shared__ char smem[];
    const uint32_t sb = smem_u32(smem);
    const int tid  = threadIdx.x;
    const int lane = tid & 31;
    const int warp = tid >> 5;
    const int grp  = warp >> 2;           // 0..3 : independent pipeline
    const int wc   = warp & 3;            // 0..3 : 32-col slice
    const int gt   = tid & 127;           // thread id within group

    float* b1s = (float*)(smem + OFF_B1);
    float* w2s = (float*)(smem + OFF_W2);
    float* HpG = (float*)(smem + OFF_HP) + grp * 128;   // [32][4]

    const uint32_t xg = sb + OFF_X + (uint32_t)grp * XGRP_SZ;

    // group barrier: 128 threads, ids 1..4
    #define BARG() asm volatile("bar.sync %0, %1;" :: "r"(grp + 1), "r"(128) : "memory")

    // ---- gather: 4 threads per edge row within the group ----
    const int grow = gt >> 2;             // 0..31
    const int gc   = gt & 3;

    auto issue_half = [&](int ch, int half, int hb) {
        if (ch < n_chunks) {
            int e = ch * CHUNK_E + grow;
            int idx = (e < n_edges) ? eidx[(half ? n_edges : 0) + e] : 0;
            const char* g = (const char*)(half ? g_dst_h : g_src_h) + (size_t)idx * 512;
            uint32_t dhi = xg + (uint32_t)hb * XBUF_SZ + (uint32_t)grow * 272;
            uint32_t dlo = dhi + XH_SZ;
            #pragma unroll
            for (int i = 0; i < 4; ++i) {
                cp16(dhi + (gc * 4 + i) * 16, g + (gc * 4 + i) * 16);
                cp16(dlo + (gc * 4 + i) * 16, g + 256 + (gc * 4 + i) * 16);
            }
        }
        CP_COMMIT();
    };

    const int cstride = gridDim.x * 4;
    int chunk = blockIdx.x * 4 + grp;
    issue_half(chunk, 0, 0);              // prologue: src half of first chunk

    // ---- one-time: W1 -> transposed fp16 (stride 528B); b1/W2 ----
    {
        __half* w = (__half*)(smem + OFF_W);
        for (int i = tid; i < K2 * D; i += NTHREADS) {
            int k = i >> 7;
            int n = i & 127;
            w[n * 264 + k] = __float2half_rn(W1[i]);
        }
        if (tid < 128) { b1s[tid] = b1[tid]; w2s[tid] = W2[tid]; }
    }
    const float b2v = b2[0];

    // ---- MMA geometry: warp tile 32 edges x 32 cols within group ----
    const int quad = lane >> 3, qr = lane & 7;
    const uint32_t aOff = (uint32_t)(((quad & 1) * 8 + qr) * 272 + (quad >> 1) * 16);
    const uint32_t bBase = sb + OFF_W
        + (uint32_t)((wc * 32 + (quad >> 1) * 8 + qr) * 528 + (quad & 1) * 16);

    __syncthreads();                      // W staged (one-time, CTA-wide)

    for (; chunk < n_chunks; chunk += cstride) {
        float c[2][4][4];
        #pragma unroll
        for (int mt = 0; mt < 2; ++mt)
            #pragma unroll
            for (int nt = 0; nt < 4; ++nt)
                #pragma unroll
                for (int r = 0; r < 4; ++r) c[mt][nt][r] = 0.f;

        auto mma_half = [&](int h, int hb) {
            const uint32_t aHi = xg + (uint32_t)hb * XBUF_SZ + aOff;
            const uint32_t aLo = aHi + XH_SZ;
            const uint32_t bK  = (uint32_t)h * 256;
            #pragma unroll 4
            for (int ks = 0; ks < 8; ++ks) {
                const uint32_t ko = (uint32_t)ks * 32;
                uint32_t ah[8], al[8], bh[8];
                ldsm_x4(ah,     aHi + ko);
                ldsm_x4(ah + 4, aHi + 4352 + ko);
                ldsm_x4(al,     aLo + ko);
                ldsm_x4(al + 4, aLo + 4352 + ko);
                ldsm_x4(bh,     bBase + bK + ko);
                ldsm_x4(bh + 4, bBase + 8448 + bK + ko);
                #pragma unroll
                for (int mt = 0; mt < 2; ++mt) {
                    #pragma unroll
                    for (int nt = 0; nt < 4; ++nt) {
                        uint32_t b0 = bh[(nt >> 1) * 4 + (nt & 1) * 2];
                        uint32_t b1r = bh[(nt >> 1) * 4 + (nt & 1) * 2 + 1];
                        mma16816(c[mt][nt], ah + mt * 4, b0, b1r);
                        mma16816(c[mt][nt], al + mt * 4, b0, b1r);
                    }
                }
            }
        };

        issue_half(chunk, 1, 1);          // dst half into buf1
        CP_WAIT1();                       // buf0 (src) complete
        BARG();                           // buf0 ready group-wide

        mma_half(0, 0);
        BARG();                           // buf0 reads done

        issue_half(chunk + cstride, 0, 0);    // prefetch next chunk's src
        CP_WAIT1();                       // buf1 (dst) complete
        BARG();                           // buf1 ready group-wide

        mma_half(1, 1);

        // ---- epilogue: relu + W2 dot over this warp's 32 cols ----
        {
            const int tq = lane >> 2;
            const int tk = lane & 3;
            float p[4];
            #pragma unroll
            for (int mt = 0; mt < 2; ++mt) {
                float s0 = 0.f, s1 = 0.f;
                #pragma unroll
                for (int nt = 0; nt < 4; ++nt) {
                    int col = wc * 32 + nt * 8 + tk * 2;
                    float ba = b1s[col], bb = b1s[col + 1];
                    float wa = w2s[col], wb = w2s[col + 1];
                    float h;
                    h = c[mt][nt][0] + ba; h = h > 0.f ? h : 0.f; s0 = fmaf(h, wa, s0);
                    h = c[mt][nt][1] + bb; h = h > 0.f ? h : 0.f; s0 = fmaf(h, wb, s0);
                    h = c[mt][nt][2] + ba; h = h > 0.f ? h : 0.f; s1 = fmaf(h, wa, s1);
                    h = c[mt][nt][3] + bb; h = h > 0.f ? h : 0.f; s1 = fmaf(h, wb, s1);
                }
                p[mt * 2]     = s0;
                p[mt * 2 + 1] = s1;
            }
            #pragma unroll
            for (int i = 0; i < 4; ++i) {
                p[i] += __shfl_xor_sync(0xffffffffu, p[i], 1);
                p[i] += __shfl_xor_sync(0xffffffffu, p[i], 2);
            }
            if (tk == 0) {
                HpG[(tq)      * 4 + wc] = p[0];
                HpG[(tq + 8)  * 4 + wc] = p[1];
                HpG[(tq + 16) * 4 + wc] = p[2];
                HpG[(tq + 24) * 4 + wc] = p[3];
            }
        }
        BARG();                           // Hpart ready; buf1 reads done

        if (wc == 0) {
            int e = chunk * CHUNK_E + lane;
            if (e < n_edges) {
                const float* hp = HpG + lane * 4;
                float s = (hp[0] + hp[1]) + (hp[2] + hp[3]) + b2v;
                out[e] = 1.f / (1.f + expf(-s));
            }
        }
        // next HpG write is 3 group-barriers away -> store race-free
    }
    #undef BARG
}

extern "C" void kernel_launch(void* const* d_in, const int* in_sizes, int n_in,
                              void* d_out, int out_size)
{
    const float* src = (const float*)d_in[0];
    const float* dst = (const float*)d_in[1];
    const int*   ei  = (const int*)d_in[2];
    const float* W1  = (const float*)d_in[3];
    const float* b1  = (const float*)d_in[4];
    const float* W2  = (const float*)d_in[5];
    const float* b2  = (const float*)d_in[6];
    float*       out = (float*)d_out;

    const int n_nodes  = in_sizes[0] / D;
    const int n_edges  = in_sizes[2] / 2;
    const int n_chunks = (n_edges + CHUNK_E - 1) / CHUNK_E;

    convert_tables<<<1480, 256>>>(src, dst, n_nodes);

    cudaFuncSetAttribute(edge_decoder_tc,
                         cudaFuncAttributeMaxDynamicSharedMemorySize, SMEM_TOTAL);
    int grid = GRID < (n_chunks + 3) / 4 ? GRID : (n_chunks + 3) / 4;
    edge_decoder_tc<<<grid, NTHREADS, SMEM_TOTAL>>>(
        ei, W1, b1, W2, b2, out, n_edges, n_chunks);
}

// round 13
// speedup vs baseline: 2.5050x; 1.5797x over previous
#include <cuda_runtime.h>
#include <cuda_fp16.h>
#include <cstdint>

// EdgeDecoder: out[e] = sigmoid( relu([src_e ; dst_e] @ W1 + b1) @ W2 + b2 )
// Round 13 (re-bench of R12; infra failure last round): single-pass fp16 MMA
// (X and W both fp16, fp32 accum), 4 independent 4-warp pipelines, 64-edge
// chunks, double-buffered cp.async, named group barriers.

#define D        128
#define K2       256
#define CHUNK_E  64                  // edges per group-chunk
#define NTHREADS 512
#define GRID     148
#define N_NODES_MAX 100000

// SMEM layout (bytes)
#define OFF_W     0                  // W^T fp16 [128 n][264 k] (stride 528B) = 67584
#define OFF_X     67584              // 4 groups x 2 bufs x (64 rows x 272B)
#define XBUF_SZ   17408
#define XGRP_SZ   34816
#define OFF_B1    (OFF_X + 4 * XGRP_SZ)   // 206848
#define OFF_W2    (OFF_B1 + 512)
#define OFF_HP    (OFF_W2 + 512)     // 4 groups x f32[64][4] = 4096
#define SMEM_TOTAL (OFF_HP + 4096)   // 211968

// Pre-converted fp16 node tables: 256B/node
__device__ __align__(16) __half g_src_h[(size_t)N_NODES_MAX * 128];
__device__ __align__(16) __half g_dst_h[(size_t)N_NODES_MAX * 128];

__device__ __forceinline__ uint32_t smem_u32(const void* p) {
    uint32_t a;
    asm("{ .reg .u64 t; cvta.to.shared.u64 t, %1; cvt.u32.u64 %0, t; }" : "=r"(a) : "l"(p));
    return a;
}
__device__ __forceinline__ void cp16(uint32_t saddr, const void* gaddr) {
    asm volatile("cp.async.cg.shared.global [%0], [%1], 16;" :: "r"(saddr), "l"(gaddr));
}
#define CP_COMMIT() asm volatile("cp.async.commit_group;" ::: "memory")
#define CP_WAIT1()  asm volatile("cp.async.wait_group 1;" ::: "memory")

__device__ __forceinline__ void ldsm_x4(uint32_t* r, uint32_t addr) {
    asm volatile("ldmatrix.sync.aligned.m8n8.x4.shared.b16 {%0,%1,%2,%3}, [%4];"
                 : "=r"(r[0]), "=r"(r[1]), "=r"(r[2]), "=r"(r[3]) : "r"(addr));
}
__device__ __forceinline__ void mma16816(float c[4], const uint32_t a[4],
                                         uint32_t b0, uint32_t b1) {
    asm volatile(
        "mma.sync.aligned.m16n8k16.row.col.f32.f16.f16.f32 "
        "{%0,%1,%2,%3}, {%4,%5,%6,%7}, {%8,%9}, {%0,%1,%2,%3};\n"
        : "+f"(c[0]), "+f"(c[1]), "+f"(c[2]), "+f"(c[3])
        : "r"(a[0]), "r"(a[1]), "r"(a[2]), "r"(a[3]), "r"(b0), "r"(b1));
}

// ---------------- prepass: fp32 tables -> fp16 tables ----------------
__global__ void convert_tables(const float* __restrict__ src,
                               const float* __restrict__ dst, int n_nodes)
{
    const int per_tab = n_nodes * 32;     // float4 per table
    for (int v = blockIdx.x * blockDim.x + threadIdx.x; v < 2 * per_tab;
         v += gridDim.x * blockDim.x) {
        const float4* tab = (const float4*)(v < per_tab ? src : dst);
        __half* ot = (v < per_tab) ? g_src_h : g_dst_h;
        int u = (v < per_tab) ? v : v - per_tab;
        int node = u >> 5, q = u & 31;
        float4 x = tab[u];
        __half2* oh = (__half2*)(ot + (size_t)node * 128 + q * 4);
        oh[0] = __halves2half2(__float2half_rn(x.x), __float2half_rn(x.y));
        oh[1] = __halves2half2(__float2half_rn(x.z), __float2half_rn(x.w));
    }
}

// ---------------- main kernel ----------------
__global__ __launch_bounds__(NTHREADS, 1)
void edge_decoder_tc(const int* __restrict__ eidx,
                     const float* __restrict__ W1,
                     const float* __restrict__ b1,
                     const float* __restrict__ W2,
                     const float* __restrict__ b2,
                     float* __restrict__ out,
                     int n_edges, int n_chunks)
{
    extern __shared__ char smem[];
    const uint32_t sb = smem_u32(smem);
    const int tid  = threadIdx.x;
    const int lane = tid & 31;
    const int warp = tid >> 5;
    const int grp  = warp >> 2;           // 0..3 : independent pipeline
    const int wc   = warp & 3;            // 0..3 : 32-col slice
    const int gt   = tid & 127;           // thread id within group

    float* b1s = (float*)(smem + OFF_B1);
    float* w2s = (float*)(smem + OFF_W2);
    float* HpG = (float*)(smem + OFF_HP) + grp * 256;   // [64][4]

    const uint32_t xg = sb + OFF_X + (uint32_t)grp * XGRP_SZ;

    #define BARG() asm volatile("bar.sync %0, %1;" :: "r"(grp + 1), "r"(128) : "memory")

    // ---- gather: 2 threads per edge row (256B each row) ----
    const int grow = gt >> 1;             // 0..63
    const int gc   = gt & 1;              // 128B slice

    auto issue_half = [&](int ch, int half, int hb) {
        if (ch < n_chunks) {
            int e = ch * CHUNK_E + grow;
            int idx = (e < n_edges) ? eidx[(half ? n_edges : 0) + e] : 0;
            const char* g = (const char*)(half ? g_dst_h : g_src_h) + (size_t)idx * 256;
            uint32_t d = xg + (uint32_t)hb * XBUF_SZ + (uint32_t)grow * 272;
            #pragma unroll
            for (int i = 0; i < 8; ++i)
                cp16(d + (gc * 8 + i) * 16, g + (gc * 8 + i) * 16);
        }
        CP_COMMIT();
    };

    const int cstride = gridDim.x * 4;
    int chunk = blockIdx.x * 4 + grp;
    issue_half(chunk, 0, 0);              // prologue: src half of first chunk

    // ---- one-time: W1 -> transposed fp16 (stride 528B); b1/W2 ----
    {
        __half* w = (__half*)(smem + OFF_W);
        for (int i = tid; i < K2 * D; i += NTHREADS) {
            int k = i >> 7;
            int n = i & 127;
            w[n * 264 + k] = __float2half_rn(W1[i]);
        }
        if (tid < 128) { b1s[tid] = b1[tid]; w2s[tid] = W2[tid]; }
    }
    const float b2v = b2[0];

    // ---- MMA geometry: warp tile 64 edges x 32 cols within group ----
    const int quad = lane >> 3, qr = lane & 7;
    const uint32_t aOff = (uint32_t)(((quad & 1) * 8 + qr) * 272 + (quad >> 1) * 16);
    const uint32_t bBase = sb + OFF_W
        + (uint32_t)((wc * 32 + (quad >> 1) * 8 + qr) * 528 + (quad & 1) * 16);

    __syncthreads();                      // W staged (one-time, CTA-wide)

    for (; chunk < n_chunks; chunk += cstride) {
        float c[4][4][4];
        #pragma unroll
        for (int mt = 0; mt < 4; ++mt)
            #pragma unroll
            for (int nt = 0; nt < 4; ++nt)
                #pragma unroll
                for (int r = 0; r < 4; ++r) c[mt][nt][r] = 0.f;

        auto mma_half = [&](int h, int hb) {
            const uint32_t aBase = xg + (uint32_t)hb * XBUF_SZ + aOff;
            const uint32_t bK    = (uint32_t)h * 256;
            #pragma unroll 4
            for (int ks = 0; ks < 8; ++ks) {
                const uint32_t ko = (uint32_t)ks * 32;
                uint32_t ah[16], bh[8];
                #pragma unroll
                for (int mt = 0; mt < 4; ++mt)
                    ldsm_x4(ah + mt * 4, aBase + (uint32_t)mt * 4352 + ko);
                ldsm_x4(bh,     bBase + bK + ko);
                ldsm_x4(bh + 4, bBase + 8448 + bK + ko);
                #pragma unroll
                for (int mt = 0; mt < 4; ++mt) {
                    #pragma unroll
                    for (int nt = 0; nt < 4; ++nt) {
                        uint32_t b0 = bh[(nt >> 1) * 4 + (nt & 1) * 2];
                        uint32_t b1r = bh[(nt >> 1) * 4 + (nt & 1) * 2 + 1];
                        mma16816(c[mt][nt], ah + mt * 4, b0, b1r);
                    }
                }
            }
        };

        issue_half(chunk, 1, 1);          // dst half into buf1
        CP_WAIT1();                       // buf0 (src) complete
        BARG();                           // buf0 ready group-wide

        mma_half(0, 0);
        BARG();                           // buf0 reads done

        issue_half(chunk + cstride, 0, 0);    // prefetch next chunk's src
        CP_WAIT1();                       // buf1 (dst) complete
        BARG();                           // buf1 ready group-wide

        mma_half(1, 1);

        // ---- epilogue: relu + W2 dot over this warp's 32 cols ----
        {
            const int tq = lane >> 2;
            const int tk = lane & 3;
            #pragma unroll
            for (int mt = 0; mt < 4; ++mt) {
                float s0 = 0.f, s1 = 0.f;
                #pragma unroll
                for (int nt = 0; nt < 4; ++nt) {
                    int col = wc * 32 + nt * 8 + tk * 2;
                    float ba = b1s[col], bb = b1s[col + 1];
                    float wa = w2s[col], wb = w2s[col + 1];
                    float h;
                    h = c[mt][nt][0] + ba; h = h > 0.f ? h : 0.f; s0 = fmaf(h, wa, s0);
                    h = c[mt][nt][1] + bb; h = h > 0.f ? h : 0.f; s0 = fmaf(h, wb, s0);
                    h = c[mt][nt][2] + ba; h = h > 0.f ? h : 0.f; s1 = fmaf(h, wa, s1);
                    h = c[mt][nt][3] + bb; h = h > 0.f ? h : 0.f; s1 = fmaf(h, wb, s1);
                }
                s0 += __shfl_xor_sync(0xffffffffu, s0, 1);
                s0 += __shfl_xor_sync(0xffffffffu, s0, 2);
                s1 += __shfl_xor_sync(0xffffffffu, s1, 1);
                s1 += __shfl_xor_sync(0xffffffffu, s1, 2);
                if (tk == 0) {
                    HpG[(mt * 16 + tq)     * 4 + wc] = s0;
                    HpG[(mt * 16 + tq + 8) * 4 + wc] = s1;
                }
            }
        }
        BARG();                           // Hpart ready; buf1 reads done

        if (wc < 2) {
            int r = wc * 32 + lane;
            int e = chunk * CHUNK_E + r;
            if (e < n_edges) {
                const float* hp = HpG + r * 4;
                float s = (hp[0] + hp[1]) + (hp[2] + hp[3]) + b2v;
                out[e] = 1.f / (1.f + expf(-s));
            }
        }
        // next HpG write is 3 group-barriers away -> store race-free
    }
    #undef BARG
}

extern "C" void kernel_launch(void* const* d_in, const int* in_sizes, int n_in,
                              void* d_out, int out_size)
{
    const float* src = (const float*)d_in[0];
    const float* dst = (const float*)d_in[1];
    const int*   ei  = (const int*)d_in[2];
    const float* W1  = (const float*)d_in[3];
    const float* b1  = (const float*)d_in[4];
    const float* W2  = (const float*)d_in[5];
    const float* b2  = (const float*)d_in[6];
    float*       out = (float*)d_out;

    const int n_nodes  = in_sizes[0] / D;
    const int n_edges  = in_sizes[2] / 2;
    const int n_chunks = (n_edges + CHUNK_E - 1) / CHUNK_E;

    convert_tables<<<1480, 256>>>(src, dst, n_nodes);

    cudaFuncSetAttribute(edge_decoder_tc,
                         cudaFuncAttributeMaxDynamicSharedMemorySize, SMEM_TOTAL);
    int grid = GRID < (n_chunks + 3) / 4 ? GRID : (n_chunks + 3) / 4;
    edge_decoder_tc<<<grid, NTHREADS, SMEM_TOTAL>>>(
        ei, W1, b1, W2, b2, out, n_edges, n_chunks);
}

// round 14
// speedup vs baseline: 2.7271x; 1.0887x over previous
#include <cuda_runtime.h>
#include <cuda_fp16.h>
#include <cstdint>

// EdgeDecoder: out[e] = sigmoid( relu([src_e ; dst_e] @ W1 + b1) @ W2 + b2 )
// Round 14: R13 + edge-index prefetch (eidx LDG issued one chunk ahead, hidden
// under MMA). Single-pass fp16 MMA, 4 independent 4-warp pipelines, 64-edge
// chunks, double-buffered cp.async, named group barriers.

#define D        128
#define K2       256
#define CHUNK_E  64                  // edges per group-chunk
#define NTHREADS 512
#define GRID     148
#define N_NODES_MAX 100000

// SMEM layout (bytes)
#define OFF_W     0                  // W^T fp16 [128 n][264 k] (stride 528B) = 67584
#define OFF_X     67584              // 4 groups x 2 bufs x (64 rows x 272B)
#define XBUF_SZ   17408
#define XGRP_SZ   34816
#define OFF_B1    (OFF_X + 4 * XGRP_SZ)   // 206848
#define OFF_W2    (OFF_B1 + 512)
#define OFF_HP    (OFF_W2 + 512)     // 4 groups x f32[64][4] = 4096
#define SMEM_TOTAL (OFF_HP + 4096)   // 211968

// Pre-converted fp16 node tables: 256B/node
__device__ __align__(16) __half g_src_h[(size_t)N_NODES_MAX * 128];
__device__ __align__(16) __half g_dst_h[(size_t)N_NODES_MAX * 128];

__device__ __forceinline__ uint32_t smem_u32(const void* p) {
    uint32_t a;
    asm("{ .reg .u64 t; cvta.to.shared.u64 t, %1; cvt.u32.u64 %0, t; }" : "=r"(a) : "l"(p));
    return a;
}
__device__ __forceinline__ void cp16(uint32_t saddr, const void* gaddr) {
    asm volatile("cp.async.cg.shared.global [%0], [%1], 16;" :: "r"(saddr), "l"(gaddr));
}
#define CP_COMMIT() asm volatile("cp.async.commit_group;" ::: "memory")
#define CP_WAIT1()  asm volatile("cp.async.wait_group 1;" ::: "memory")

__device__ __forceinline__ void ldsm_x4(uint32_t* r, uint32_t addr) {
    asm volatile("ldmatrix.sync.aligned.m8n8.x4.shared.b16 {%0,%1,%2,%3}, [%4];"
                 : "=r"(r[0]), "=r"(r[1]), "=r"(r[2]), "=r"(r[3]) : "r"(addr));
}
__device__ __forceinline__ void mma16816(float c[4], const uint32_t a[4],
                                         uint32_t b0, uint32_t b1) {
    asm volatile(
        "mma.sync.aligned.m16n8k16.row.col.f32.f16.f16.f32 "
        "{%0,%1,%2,%3}, {%4,%5,%6,%7}, {%8,%9}, {%0,%1,%2,%3};\n"
        : "+f"(c[0]), "+f"(c[1]), "+f"(c[2]), "+f"(c[3])
        : "r"(a[0]), "r"(a[1]), "r"(a[2]), "r"(a[3]), "r"(b0), "r"(b1));
}

// ---------------- prepass: fp32 tables -> fp16 tables ----------------
__global__ void convert_tables(const float* __restrict__ src,
                               const float* __restrict__ dst, int n_nodes)
{
    const int per_tab = n_nodes * 32;     // float4 per table
    for (int v = blockIdx.x * blockDim.x + threadIdx.x; v < 2 * per_tab;
         v += gridDim.x * blockDim.x) {
        const float4* tab = (const float4*)(v < per_tab ? src : dst);
        __half* ot = (v < per_tab) ? g_src_h : g_dst_h;
        int u = (v < per_tab) ? v : v - per_tab;
        int node = u >> 5, q = u & 31;
        float4 x = tab[u];
        __half2* oh = (__half2*)(ot + (size_t)node * 128 + q * 4);
        oh[0] = __halves2half2(__float2half_rn(x.x), __float2half_rn(x.y));
        oh[1] = __halves2half2(__float2half_rn(x.z), __float2half_rn(x.w));
    }
}

// ---------------- main kernel ----------------
__global__ __launch_bounds__(NTHREADS, 1)
void edge_decoder_tc(const int* __restrict__ eidx,
                     const float* __restrict__ W1,
                     const float* __restrict__ b1,
                     const float* __restrict__ W2,
                     const float* __restrict__ b2,
                     float* __restrict__ out,
                     int n_edges, int n_chunks)
{
    extern __shared__ char smem[];
    const uint32_t sb = smem_u32(smem);
    const int tid  = threadIdx.x;
    const int lane = tid & 31;
    const int warp = tid >> 5;
    const int grp  = warp >> 2;           // 0..3 : independent pipeline
    const int wc   = warp & 3;            // 0..3 : 32-col slice
    const int gt   = tid & 127;           // thread id within group

    float* b1s = (float*)(smem + OFF_B1);
    float* w2s = (float*)(smem + OFF_W2);
    float* HpG = (float*)(smem + OFF_HP) + grp * 256;   // [64][4]

    const uint32_t xg = sb + OFF_X + (uint32_t)grp * XGRP_SZ;

    #define BARG() asm volatile("bar.sync %0, %1;" :: "r"(grp + 1), "r"(128) : "memory")

    // ---- gather: 2 threads per edge row (256B each row) ----
    const int grow = gt >> 1;             // 0..63
    const int gc   = gt & 1;              // 128B slice

    // index prefetch: LDG issued well before the cp.async that consumes it
    auto ld_idx = [&](int ch, int half) -> int {
        int idx = 0;
        if (ch < n_chunks) {
            int e = ch * CHUNK_E + grow;
            if (e < n_edges) idx = eidx[(half ? n_edges : 0) + e];
        }
        return idx;
    };

    auto issue_half = [&](int ch, int half, int hb, int idx) {
        if (ch < n_chunks) {
            const char* g = (const char*)(half ? g_dst_h : g_src_h) + (size_t)idx * 256;
            uint32_t d = xg + (uint32_t)hb * XBUF_SZ + (uint32_t)grow * 272;
            #pragma unroll
            for (int i = 0; i < 8; ++i)
                cp16(d + (gc * 8 + i) * 16, g + (gc * 8 + i) * 16);
        }
        CP_COMMIT();
    };

    const int cstride = gridDim.x * 4;
    int chunk = blockIdx.x * 4 + grp;
    issue_half(chunk, 0, 0, ld_idx(chunk, 0));    // prologue: src of first chunk
    int cur_d = ld_idx(chunk, 1);                 // this chunk's dst index
    int nxt_s = ld_idx(chunk + cstride, 0);       // next chunk's src index

    // ---- one-time: W1 -> transposed fp16 (stride 528B); b1/W2 ----
    {
        __half* w = (__half*)(smem + OFF_W);
        for (int i = tid; i < K2 * D; i += NTHREADS) {
            int k = i >> 7;
            int n = i & 127;
            w[n * 264 + k] = __float2half_rn(W1[i]);
        }
        if (tid < 128) { b1s[tid] = b1[tid]; w2s[tid] = W2[tid]; }
    }
    const float b2v = b2[0];

    // ---- MMA geometry: warp tile 64 edges x 32 cols within group ----
    const int quad = lane >> 3, qr = lane & 7;
    const uint32_t aOff = (uint32_t)(((quad & 1) * 8 + qr) * 272 + (quad >> 1) * 16);
    const uint32_t bBase = sb + OFF_W
        + (uint32_t)((wc * 32 + (quad >> 1) * 8 + qr) * 528 + (quad & 1) * 16);

    __syncthreads();                      // W staged (one-time, CTA-wide)

    for (; chunk < n_chunks; chunk += cstride) {
        float c[4][4][4];
        #pragma unroll
        for (int mt = 0; mt < 4; ++mt)
            #pragma unroll
            for (int nt = 0; nt < 4; ++nt)
                #pragma unroll
                for (int r = 0; r < 4; ++r) c[mt][nt][r] = 0.f;

        auto mma_half = [&](int h, int hb) {
            const uint32_t aBase = xg + (uint32_t)hb * XBUF_SZ + aOff;
            const uint32_t bK    = (uint32_t)h * 256;
            #pragma unroll 4
            for (int ks = 0; ks < 8; ++ks) {
                const uint32_t ko = (uint32_t)ks * 32;
                uint32_t ah[16], bh[8];
                #pragma unroll
                for (int mt = 0; mt < 4; ++mt)
                    ldsm_x4(ah + mt * 4, aBase + (uint32_t)mt * 4352 + ko);
                ldsm_x4(bh,     bBase + bK + ko);
                ldsm_x4(bh + 4, bBase + 8448 + bK + ko);
                #pragma unroll
                for (int mt = 0; mt < 4; ++mt) {
                    #pragma unroll
                    for (int nt = 0; nt < 4; ++nt) {
                        uint32_t b0 = bh[(nt >> 1) * 4 + (nt & 1) * 2];
                        uint32_t b1r = bh[(nt >> 1) * 4 + (nt & 1) * 2 + 1];
                        mma16816(c[mt][nt], ah + mt * 4, b0, b1r);
                    }
                }
            }
        };

        issue_half(chunk, 1, 1, cur_d);   // dst half into buf1 (idx prefetched)
        CP_WAIT1();                       // buf0 (src) complete
        BARG();                           // buf0 ready group-wide

        int nxt_d = ld_idx(chunk + cstride, 1);   // hide LDG under mma(0)
        mma_half(0, 0);
        BARG();                           // buf0 reads done

        issue_half(chunk + cstride, 0, 0, nxt_s); // next src (idx prefetched)
        CP_WAIT1();                       // buf1 (dst) complete
        BARG();                           // buf1 ready group-wide

        int nxt2_s = ld_idx(chunk + 2 * cstride, 0);  // hide LDG under mma(1)
        mma_half(1, 1);

        // ---- epilogue: relu + W2 dot over this warp's 32 cols ----
        {
            const int tq = lane >> 2;
            const int tk = lane & 3;
            #pragma unroll
            for (int mt = 0; mt < 4; ++mt) {
                float s0 = 0.f, s1 = 0.f;
                #pragma unroll
                for (int nt = 0; nt < 4; ++nt) {
                    int col = wc * 32 + nt * 8 + tk * 2;
                    float ba = b1s[col], bb = b1s[col + 1];
                    float wa = w2s[col], wb = w2s[col + 1];
                    float h;
                    h = c[mt][nt][0] + ba; h = h > 0.f ? h : 0.f; s0 = fmaf(h, wa, s0);
                    h = c[mt][nt][1] + bb; h = h > 0.f ? h : 0.f; s0 = fmaf(h, wb, s0);
                    h = c[mt][nt][2] + ba; h = h > 0.f ? h : 0.f; s1 = fmaf(h, wa, s1);
                    h = c[mt][nt][3] + bb; h = h > 0.f ? h : 0.f; s1 = fmaf(h, wb, s1);
                }
                s0 += __shfl_xor_sync(0xffffffffu, s0, 1);
                s0 += __shfl_xor_sync(0xffffffffu, s0, 2);
                s1 += __shfl_xor_sync(0xffffffffu, s1, 1);
                s1 += __shfl_xor_sync(0xffffffffu, s1, 2);
                if (tk == 0) {
                    HpG[(mt * 16 + tq)     * 4 + wc] = s0;
                    HpG[(mt * 16 + tq + 8) * 4 + wc] = s1;
                }
            }
        }
        BARG();                           // Hpart ready; buf1 reads done

        if (wc < 2) {
            int r = wc * 32 + lane;
            int e = chunk * CHUNK_E + r;
            if (e < n_edges) {
                const float* hp = HpG + r * 4;
                float s = (hp[0] + hp[1]) + (hp[2] + hp[3]) + b2v;
                out[e] = 1.f / (1.f + expf(-s));
            }
        }
        // next HpG write is 3 group-barriers away -> store race-free

        cur_d = nxt_d;                    // rotate prefetched indices
        nxt_s = nxt2_s;
    }
    #undef BARG
}

extern "C" void kernel_launch(void* const* d_in, const int* in_sizes, int n_in,
                              void* d_out, int out_size)
{
    const float* src = (const float*)d_in[0];
    const float* dst = (const float*)d_in[1];
    const int*   ei  = (const int*)d_in[2];
    const float* W1  = (const float*)d_in[3];
    const float* b1  = (const float*)d_in[4];
    const float* W2  = (const float*)d_in[5];
    const float* b2  = (const float*)d_in[6];
    float*       out = (float*)d_out;

    const int n_nodes  = in_sizes[0] / D;
    const int n_edges  = in_sizes[2] / 2;
    const int n_chunks = (n_edges + CHUNK_E - 1) / CHUNK_E;

    convert_tables<<<1480, 256>>>(src, dst, n_nodes);

    cudaFuncSetAttribute(edge_decoder_tc,
                         cudaFuncAttributeMaxDynamicSharedMemorySize, SMEM_TOTAL);
    int grid = GRID < (n_chunks + 3) / 4 ? GRID : (n_chunks + 3) / 4;
    edge_decoder_tc<<<grid, NTHREADS, SMEM_TOTAL>>>(
        ei, W1, b1, W2, b2, out, n_edges, n_chunks);
}

// round 15
// speedup vs baseline: 2.9498x; 1.0817x over previous
#include <cuda_runtime.h>
#include <cuda_fp16.h>
#include <cstdint>

// EdgeDecoder: out[e] = sigmoid( relu([src_e ; dst_e] @ W1 + b1) @ W2 + b2 )
// Round 15: 8 independent 2-warp pipelines per CTA (32-edge chunks, warp tile
// 32x64), single-pass fp16 MMA, double-buffered cp.async, index prefetch,
// named group barriers. Prepass fp16 node tables.

#define D        128
#define K2       256
#define CHUNK_E  32                  // edges per group-chunk
#define NTHREADS 512
#define GRID     148
#define N_NODES_MAX 100000

// SMEM layout (bytes)
#define OFF_W     0                  // W^T fp16 [128 n][264 k] (stride 528B) = 67584
#define OFF_X     67584              // 8 groups x 2 bufs x (32 rows x 272B)
#define XBUF_SZ   8704
#define XGRP_SZ   17408
#define OFF_B1    (OFF_X + 8 * XGRP_SZ)   // 206848
#define OFF_W2    (OFF_B1 + 512)
#define OFF_HP    (OFF_W2 + 512)     // 8 groups x f32[32][2] = 2048
#define SMEM_TOTAL (OFF_HP + 2048)   // 209920

// Pre-converted fp16 node tables: 256B/node
__device__ __align__(16) __half g_src_h[(size_t)N_NODES_MAX * 128];
__device__ __align__(16) __half g_dst_h[(size_t)N_NODES_MAX * 128];

__device__ __forceinline__ uint32_t smem_u32(const void* p) {
    uint32_t a;
    asm("{ .reg .u64 t; cvta.to.shared.u64 t, %1; cvt.u32.u64 %0, t; }" : "=r"(a) : "l"(p));
    return a;
}
__device__ __forceinline__ void cp16(uint32_t saddr, const void* gaddr) {
    asm volatile("cp.async.cg.shared.global [%0], [%1], 16;" :: "r"(saddr), "l"(gaddr));
}
#define CP_COMMIT() asm volatile("cp.async.commit_group;" ::: "memory")
#define CP_WAIT1()  asm volatile("cp.async.wait_group 1;" ::: "memory")

__device__ __forceinline__ void ldsm_x4(uint32_t* r, uint32_t addr) {
    asm volatile("ldmatrix.sync.aligned.m8n8.x4.shared.b16 {%0,%1,%2,%3}, [%4];"
                 : "=r"(r[0]), "=r"(r[1]), "=r"(r[2]), "=r"(r[3]) : "r"(addr));
}
__device__ __forceinline__ void mma16816(float c[4], const uint32_t a[4],
                                         uint32_t b0, uint32_t b1) {
    asm volatile(
        "mma.sync.aligned.m16n8k16.row.col.f32.f16.f16.f32 "
        "{%0,%1,%2,%3}, {%4,%5,%6,%7}, {%8,%9}, {%0,%1,%2,%3};\n"
        : "+f"(c[0]), "+f"(c[1]), "+f"(c[2]), "+f"(c[3])
        : "r"(a[0]), "r"(a[1]), "r"(a[2]), "r"(a[3]), "r"(b0), "r"(b1));
}

// ---------------- prepass: fp32 tables -> fp16 tables ----------------
__global__ void convert_tables(const float* __restrict__ src,
                               const float* __restrict__ dst, int n_nodes)
{
    const int per_tab = n_nodes * 32;     // float4 per table
    for (int v = blockIdx.x * blockDim.x + threadIdx.x; v < 2 * per_tab;
         v += gridDim.x * blockDim.x) {
        const float4* tab = (const float4*)(v < per_tab ? src : dst);
        __half* ot = (v < per_tab) ? g_src_h : g_dst_h;
        int u = (v < per_tab) ? v : v - per_tab;
        int node = u >> 5, q = u & 31;
        float4 x = tab[u];
        __half2* oh = (__half2*)(ot + (size_t)node * 128 + q * 4);
        oh[0] = __halves2half2(__float2half_rn(x.x), __float2half_rn(x.y));
        oh[1] = __halves2half2(__float2half_rn(x.z), __float2half_rn(x.w));
    }
}

// ---------------- main kernel ----------------
__global__ __launch_bounds__(NTHREADS, 1)
void edge_decoder_tc(const int* __restrict__ eidx,
                     const float* __restrict__ W1,
                     const float* __restrict__ b1,
                     const float* __restrict__ W2,
                     const float* __restrict__ b2,
                     float* __restrict__ out,
                     int n_edges, int n_chunks)
{
    extern __shared__ char smem[];
    const uint32_t sb = smem_u32(smem);
    const int tid  = threadIdx.x;
    const int lane = tid & 31;
    const int warp = tid >> 5;
    const int grp  = warp >> 1;           // 0..7 : independent pipeline
    const int wc   = warp & 1;            // 0..1 : 64-col slice
    const int gt   = tid & 63;            // thread id within group

    float* b1s = (float*)(smem + OFF_B1);
    float* w2s = (float*)(smem + OFF_W2);
    float* HpG = (float*)(smem + OFF_HP) + grp * 64;    // [32][2]

    const uint32_t xg = sb + OFF_X + (uint32_t)grp * XGRP_SZ;

    #define BARG() asm volatile("bar.sync %0, %1;" :: "r"(grp + 1), "r"(64) : "memory")

    // ---- gather: 2 threads per edge row (256B each row) ----
    const int grow = gt >> 1;             // 0..31
    const int gc   = gt & 1;              // 128B slice

    // index prefetch: LDG issued well before the cp.async that consumes it
    auto ld_idx = [&](int ch, int half) -> int {
        int idx = 0;
        if (ch < n_chunks) {
            int e = ch * CHUNK_E + grow;
            if (e < n_edges) idx = eidx[(half ? n_edges : 0) + e];
        }
        return idx;
    };

    auto issue_half = [&](int ch, int half, int hb, int idx) {
        if (ch < n_chunks) {
            const char* g = (const char*)(half ? g_dst_h : g_src_h) + (size_t)idx * 256;
            uint32_t d = xg + (uint32_t)hb * XBUF_SZ + (uint32_t)grow * 272;
            #pragma unroll
            for (int i = 0; i < 8; ++i)
                cp16(d + (gc * 8 + i) * 16, g + (gc * 8 + i) * 16);
        }
        CP_COMMIT();
    };

    const int cstride = gridDim.x * 8;
    int chunk = blockIdx.x * 8 + grp;
    issue_half(chunk, 0, 0, ld_idx(chunk, 0));    // prologue: src of first chunk
    int cur_d = ld_idx(chunk, 1);                 // this chunk's dst index
    int nxt_s = ld_idx(chunk + cstride, 0);       // next chunk's src index

    // ---- one-time: W1 -> transposed fp16 (stride 528B); b1/W2 ----
    {
        __half* w = (__half*)(smem + OFF_W);
        for (int i = tid; i < K2 * D; i += NTHREADS) {
            int k = i >> 7;
            int n = i & 127;
            w[n * 264 + k] = __float2half_rn(W1[i]);
        }
        if (tid < 128) { b1s[tid] = b1[tid]; w2s[tid] = W2[tid]; }
    }
    const float b2v = b2[0];

    // ---- MMA geometry: warp tile 32 edges x 64 cols ----
    const int quad = lane >> 3, qr = lane & 7;
    const uint32_t aOff = (uint32_t)(((quad & 1) * 8 + qr) * 272 + (quad >> 1) * 16);
    const uint32_t bBase = sb + OFF_W
        + (uint32_t)((wc * 64 + (quad >> 1) * 8 + qr) * 528 + (quad & 1) * 16);

    __syncthreads();                      // W staged (one-time, CTA-wide)

    for (; chunk < n_chunks; chunk += cstride) {
        float c[2][8][4];
        #pragma unroll
        for (int mt = 0; mt < 2; ++mt)
            #pragma unroll
            for (int nt = 0; nt < 8; ++nt)
                #pragma unroll
                for (int r = 0; r < 4; ++r) c[mt][nt][r] = 0.f;

        auto mma_half = [&](int h, int hb) {
            const uint32_t aBase = xg + (uint32_t)hb * XBUF_SZ + aOff;
            const uint32_t bK    = (uint32_t)h * 256;
            #pragma unroll 4
            for (int ks = 0; ks < 8; ++ks) {
                const uint32_t ko = (uint32_t)ks * 32;
                uint32_t ah[8], bh[16];
                ldsm_x4(ah,     aBase + ko);
                ldsm_x4(ah + 4, aBase + 4352 + ko);
                #pragma unroll
                for (int j = 0; j < 4; ++j)
                    ldsm_x4(bh + j * 4, bBase + (uint32_t)j * 8448 + bK + ko);
                #pragma unroll
                for (int mt = 0; mt < 2; ++mt) {
                    #pragma unroll
                    for (int nt = 0; nt < 8; ++nt) {
                        uint32_t b0 = bh[(nt >> 1) * 4 + (nt & 1) * 2];
                        uint32_t b1r = bh[(nt >> 1) * 4 + (nt & 1) * 2 + 1];
                        mma16816(c[mt][nt], ah + mt * 4, b0, b1r);
                    }
                }
            }
        };

        issue_half(chunk, 1, 1, cur_d);   // dst half into buf1 (idx prefetched)
        CP_WAIT1();                       // buf0 (src) complete
        BARG();                           // buf0 ready group-wide

        int nxt_d = ld_idx(chunk + cstride, 1);   // hide LDG under mma(0)
        mma_half(0, 0);
        BARG();                           // buf0 reads done

        issue_half(chunk + cstride, 0, 0, nxt_s); // next src (idx prefetched)
        CP_WAIT1();                       // buf1 (dst) complete
        BARG();                           // buf1 ready group-wide

        int nxt2_s = ld_idx(chunk + 2 * cstride, 0);  // hide LDG under mma(1)
        mma_half(1, 1);

        // ---- epilogue: relu + W2 dot over this warp's 64 cols ----
        {
            const int tq = lane >> 2;
            const int tk = lane & 3;
            #pragma unroll
            for (int mt = 0; mt < 2; ++mt) {
                float s0 = 0.f, s1 = 0.f;
                #pragma unroll
                for (int nt = 0; nt < 8; ++nt) {
                    int col = wc * 64 + nt * 8 + tk * 2;
                    float ba = b1s[col], bb = b1s[col + 1];
                    float wa = w2s[col], wb = w2s[col + 1];
                    float h;
                    h = c[mt][nt][0] + ba; h = h > 0.f ? h : 0.f; s0 = fmaf(h, wa, s0);
                    h = c[mt][nt][1] + bb; h = h > 0.f ? h : 0.f; s0 = fmaf(h, wb, s0);
                    h = c[mt][nt][2] + ba; h = h > 0.f ? h : 0.f; s1 = fmaf(h, wa, s1);
                    h = c[mt][nt][3] + bb; h = h > 0.f ? h : 0.f; s1 = fmaf(h, wb, s1);
                }
                s0 += __shfl_xor_sync(0xffffffffu, s0, 1);
                s0 += __shfl_xor_sync(0xffffffffu, s0, 2);
                s1 += __shfl_xor_sync(0xffffffffu, s1, 1);
                s1 += __shfl_xor_sync(0xffffffffu, s1, 2);
                if (tk == 0) {
                    HpG[(mt * 16 + tq)     * 2 + wc] = s0;
                    HpG[(mt * 16 + tq + 8) * 2 + wc] = s1;
                }
            }
        }
        BARG();                           // Hpart ready; buf1 reads done

        if (wc == 0) {
            int e = chunk * CHUNK_E + lane;
            if (e < n_edges) {
                float s = HpG[lane * 2] + HpG[lane * 2 + 1] + b2v;
                out[e] = 1.f / (1.f + expf(-s));
            }
        }
        // next HpG write is 3 group-barriers away -> store race-free

        cur_d = nxt_d;                    // rotate prefetched indices
        nxt_s = nxt2_s;
    }
    #undef BARG
}

extern "C" void kernel_launch(void* const* d_in, const int* in_sizes, int n_in,
                              void* d_out, int out_size)
{
    const float* src = (const float*)d_in[0];
    const float* dst = (const float*)d_in[1];
    const int*   ei  = (const int*)d_in[2];
    const float* W1  = (const float*)d_in[3];
    const float* b1  = (const float*)d_in[4];
    const float* W2  = (const float*)d_in[5];
    const float* b2  = (const float*)d_in[6];
    float*       out = (float*)d_out;

    const int n_nodes  = in_sizes[0] / D;
    const int n_edges  = in_sizes[2] / 2;
    const int n_chunks = (n_edges + CHUNK_E - 1) / CHUNK_E;

    convert_tables<<<1480, 256>>>(src, dst, n_nodes);

    cudaFuncSetAttribute(edge_decoder_tc,
                         cudaFuncAttributeMaxDynamicSharedMemorySize, SMEM_TOTAL);
    int grid = GRID < (n_chunks + 7) / 8 ? GRID : (n_chunks + 7) / 8;
    edge_decoder_tc<<<grid, NTHREADS, SMEM_TOTAL>>>(
        ei, W1, b1, W2, b2, out, n_edges, n_chunks);
}

// round 16
// speedup vs baseline: 2.9504x; 1.0002x over previous
#include <cuda_runtime.h>
#include <cuda_fp16.h>
#include <cstdint>

// EdgeDecoder: out[e] = sigmoid( relu([src_e ; dst_e] @ W1 + b1) @ W2 + b2 )
// Round 16: R15 + inner-loop register relief: B fragments loaded in two 8-reg
// batches per k-step so ptxas can software-pipeline LDSM under MMA.
// 8 independent 2-warp pipelines, 32-edge chunks, single-pass fp16 MMA.

#define D        128
#define K2       256
#define CHUNK_E  32                  // edges per group-chunk
#define NTHREADS 512
#define GRID     148
#define N_NODES_MAX 100000

// SMEM layout (bytes)
#define OFF_W     0                  // W^T fp16 [128 n][264 k] (stride 528B) = 67584
#define OFF_X     67584              // 8 groups x 2 bufs x (32 rows x 272B)
#define XBUF_SZ   8704
#define XGRP_SZ   17408
#define OFF_B1    (OFF_X + 8 * XGRP_SZ)   // 206848
#define OFF_W2    (OFF_B1 + 512)
#define OFF_HP    (OFF_W2 + 512)     // 8 groups x f32[32][2] = 2048
#define SMEM_TOTAL (OFF_HP + 2048)   // 209920

// Pre-converted fp16 node tables: 256B/node
__device__ __align__(16) __half g_src_h[(size_t)N_NODES_MAX * 128];
__device__ __align__(16) __half g_dst_h[(size_t)N_NODES_MAX * 128];

__device__ __forceinline__ uint32_t smem_u32(const void* p) {
    uint32_t a;
    asm("{ .reg .u64 t; cvta.to.shared.u64 t, %1; cvt.u32.u64 %0, t; }" : "=r"(a) : "l"(p));
    return a;
}
__device__ __forceinline__ void cp16(uint32_t saddr, const void* gaddr) {
    asm volatile("cp.async.cg.shared.global [%0], [%1], 16;" :: "r"(saddr), "l"(gaddr));
}
#define CP_COMMIT() asm volatile("cp.async.commit_group;" ::: "memory")
#define CP_WAIT1()  asm volatile("cp.async.wait_group 1;" ::: "memory")

__device__ __forceinline__ void ldsm_x4(uint32_t* r, uint32_t addr) {
    asm volatile("ldmatrix.sync.aligned.m8n8.x4.shared.b16 {%0,%1,%2,%3}, [%4];"
                 : "=r"(r[0]), "=r"(r[1]), "=r"(r[2]), "=r"(r[3]) : "r"(addr));
}
__device__ __forceinline__ void mma16816(float c[4], const uint32_t a[4],
                                         uint32_t b0, uint32_t b1) {
    asm volatile(
        "mma.sync.aligned.m16n8k16.row.col.f32.f16.f16.f32 "
        "{%0,%1,%2,%3}, {%4,%5,%6,%7}, {%8,%9}, {%0,%1,%2,%3};\n"
        : "+f"(c[0]), "+f"(c[1]), "+f"(c[2]), "+f"(c[3])
        : "r"(a[0]), "r"(a[1]), "r"(a[2]), "r"(a[3]), "r"(b0), "r"(b1));
}

// ---------------- prepass: fp32 tables -> fp16 tables ----------------
__global__ void convert_tables(const float* __restrict__ src,
                               const float* __restrict__ dst, int n_nodes)
{
    const int per_tab = n_nodes * 32;     // float4 per table
    for (int v = blockIdx.x * blockDim.x + threadIdx.x; v < 2 * per_tab;
         v += gridDim.x * blockDim.x) {
        const float4* tab = (const float4*)(v < per_tab ? src : dst);
        __half* ot = (v < per_tab) ? g_src_h : g_dst_h;
        int u = (v < per_tab) ? v : v - per_tab;
        int node = u >> 5, q = u & 31;
        float4 x = tab[u];
        __half2* oh = (__half2*)(ot + (size_t)node * 128 + q * 4);
        oh[0] = __halves2half2(__float2half_rn(x.x), __float2half_rn(x.y));
        oh[1] = __halves2half2(__float2half_rn(x.z), __float2half_rn(x.w));
    }
}

// ---------------- main kernel ----------------
__global__ __launch_bounds__(NTHREADS, 1)
void edge_decoder_tc(const int* __restrict__ eidx,
                     const float* __restrict__ W1,
                     const float* __restrict__ b1,
                     const float* __restrict__ W2,
                     const float* __restrict__ b2,
                     float* __restrict__ out,
                     int n_edges, int n_chunks)
{
    extern __shared__ char smem[];
    const uint32_t sb = smem_u32(smem);
    const int tid  = threadIdx.x;
    const int lane = tid & 31;
    const int warp = tid >> 5;
    const int grp  = warp >> 1;           // 0..7 : independent pipeline
    const int wc   = warp & 1;            // 0..1 : 64-col slice
    const int gt   = tid & 63;            // thread id within group

    float* b1s = (float*)(smem + OFF_B1);
    float* w2s = (float*)(smem + OFF_W2);
    float* HpG = (float*)(smem + OFF_HP) + grp * 64;    // [32][2]

    const uint32_t xg = sb + OFF_X + (uint32_t)grp * XGRP_SZ;

    #define BARG() asm volatile("bar.sync %0, %1;" :: "r"(grp + 1), "r"(64) : "memory")

    // ---- gather: 2 threads per edge row (256B each row) ----
    const int grow = gt >> 1;             // 0..31
    const int gc   = gt & 1;              // 128B slice

    auto ld_idx = [&](int ch, int half) -> int {
        int idx = 0;
        if (ch < n_chunks) {
            int e = ch * CHUNK_E + grow;
            if (e < n_edges) idx = eidx[(half ? n_edges : 0) + e];
        }
        return idx;
    };

    auto issue_half = [&](int ch, int half, int hb, int idx) {
        if (ch < n_chunks) {
            const char* g = (const char*)(half ? g_dst_h : g_src_h) + (size_t)idx * 256;
            uint32_t d = xg + (uint32_t)hb * XBUF_SZ + (uint32_t)grow * 272;
            #pragma unroll
            for (int i = 0; i < 8; ++i)
                cp16(d + (gc * 8 + i) * 16, g + (gc * 8 + i) * 16);
        }
        CP_COMMIT();
    };

    const int cstride = gridDim.x * 8;
    int chunk = blockIdx.x * 8 + grp;
    issue_half(chunk, 0, 0, ld_idx(chunk, 0));    // prologue: src of first chunk
    int cur_d = ld_idx(chunk, 1);                 // this chunk's dst index
    int nxt_s = ld_idx(chunk + cstride, 0);       // next chunk's src index

    // ---- one-time: W1 -> transposed fp16 (stride 528B); b1/W2 ----
    {
        __half* w = (__half*)(smem + OFF_W);
        for (int i = tid; i < K2 * D; i += NTHREADS) {
            int k = i >> 7;
            int n = i & 127;
            w[n * 264 + k] = __float2half_rn(W1[i]);
        }
        if (tid < 128) { b1s[tid] = b1[tid]; w2s[tid] = W2[tid]; }
    }
    const float b2v = b2[0];

    // ---- MMA geometry: warp tile 32 edges x 64 cols ----
    const int quad = lane >> 3, qr = lane & 7;
    const uint32_t aOff = (uint32_t)(((quad & 1) * 8 + qr) * 272 + (quad >> 1) * 16);
    const uint32_t bBase = sb + OFF_W
        + (uint32_t)((wc * 64 + (quad >> 1) * 8 + qr) * 528 + (quad & 1) * 16);

    __syncthreads();                      // W staged (one-time, CTA-wide)

    for (; chunk < n_chunks; chunk += cstride) {
        float c[2][8][4];
        #pragma unroll
        for (int mt = 0; mt < 2; ++mt)
            #pragma unroll
            for (int nt = 0; nt < 8; ++nt)
                #pragma unroll
                for (int r = 0; r < 4; ++r) c[mt][nt][r] = 0.f;

        auto mma_half = [&](int h, int hb) {
            const uint32_t aBase = xg + (uint32_t)hb * XBUF_SZ + aOff;
            const uint32_t bK    = (uint32_t)h * 256;
            #pragma unroll 4
            for (int ks = 0; ks < 8; ++ks) {
                const uint32_t ko = (uint32_t)ks * 32;
                uint32_t ah[8], bh[8];
                ldsm_x4(ah,     aBase + ko);
                ldsm_x4(ah + 4, aBase + 4352 + ko);
                // batch 1: B tiles j=0,1 -> nt 0..3
                ldsm_x4(bh,     bBase + bK + ko);
                ldsm_x4(bh + 4, bBase + 8448 + bK + ko);
                #pragma unroll
                for (int mt = 0; mt < 2; ++mt) {
                    #pragma unroll
                    for (int nt = 0; nt < 4; ++nt) {
                        uint32_t b0 = bh[(nt >> 1) * 4 + (nt & 1) * 2];
                        uint32_t b1r = bh[(nt >> 1) * 4 + (nt & 1) * 2 + 1];
                        mma16816(c[mt][nt], ah + mt * 4, b0, b1r);
                    }
                }
                // batch 2: B tiles j=2,3 -> nt 4..7 (reuse bh regs)
                ldsm_x4(bh,     bBase + 2u * 8448 + bK + ko);
                ldsm_x4(bh + 4, bBase + 3u * 8448 + bK + ko);
                #pragma unroll
                for (int mt = 0; mt < 2; ++mt) {
                    #pragma unroll
                    for (int nt = 4; nt < 8; ++nt) {
                        uint32_t b0 = bh[((nt - 4) >> 1) * 4 + (nt & 1) * 2];
                        uint32_t b1r = bh[((nt - 4) >> 1) * 4 + (nt & 1) * 2 + 1];
                        mma16816(c[mt][nt], ah + mt * 4, b0, b1r);
                    }
                }
            }
        };

        issue_half(chunk, 1, 1, cur_d);   // dst half into buf1 (idx prefetched)
        CP_WAIT1();                       // buf0 (src) complete
        BARG();                           // buf0 ready group-wide

        int nxt_d = ld_idx(chunk + cstride, 1);   // hide LDG under mma(0)
        mma_half(0, 0);
        BARG();                           // buf0 reads done

        issue_half(chunk + cstride, 0, 0, nxt_s); // next src (idx prefetched)
        CP_WAIT1();                       // buf1 (dst) complete
        BARG();                           // buf1 ready group-wide

        int nxt2_s = ld_idx(chunk + 2 * cstride, 0);  // hide LDG under mma(1)
        mma_half(1, 1);

        // ---- epilogue: relu + W2 dot over this warp's 64 cols ----
        {
            const int tq = lane >> 2;
            const int tk = lane & 3;
            #pragma unroll
            for (int mt = 0; mt < 2; ++mt) {
                float s0 = 0.f, s1 = 0.f;
                #pragma unroll
                for (int nt = 0; nt < 8; ++nt) {
                    int col = wc * 64 + nt * 8 + tk * 2;
                    float ba = b1s[col], bb = b1s[col + 1];
                    float wa = w2s[col], wb = w2s[col + 1];
                    float h;
                    h = c[mt][nt][0] + ba; h = h > 0.f ? h : 0.f; s0 = fmaf(h, wa, s0);
                    h = c[mt][nt][1] + bb; h = h > 0.f ? h : 0.f; s0 = fmaf(h, wb, s0);
                    h = c[mt][nt][2] + ba; h = h > 0.f ? h : 0.f; s1 = fmaf(h, wa, s1);
                    h = c[mt][nt][3] + bb; h = h > 0.f ? h : 0.f; s1 = fmaf(h, wb, s1);
                }
                s0 += __shfl_xor_sync(0xffffffffu, s0, 1);
                s0 += __shfl_xor_sync(0xffffffffu, s0, 2);
                s1 += __shfl_xor_sync(0xffffffffu, s1, 1);
                s1 += __shfl_xor_sync(0xffffffffu, s1, 2);
                if (tk == 0) {
                    HpG[(mt * 16 + tq)     * 2 + wc] = s0;
                    HpG[(mt * 16 + tq + 8) * 2 + wc] = s1;
                }
            }
        }
        BARG();                           // Hpart ready; buf1 reads done

        if (wc == 0) {
            int e = chunk * CHUNK_E + lane;
            if (e < n_edges) {
                float s = HpG[lane * 2] + HpG[lane * 2 + 1] + b2v;
                out[e] = 1.f / (1.f + expf(-s));
            }
        }
        // next HpG write is 3 group-barriers away -> store race-free

        cur_d = nxt_d;                    // rotate prefetched indices
        nxt_s = nxt2_s;
    }
    #undef BARG
}

extern "C" void kernel_launch(void* const* d_in, const int* in_sizes, int n_in,
                              void* d_out, int out_size)
{
    const float* src = (const float*)d_in[0];
    const float* dst = (const float*)d_in[1];
    const int*   ei  = (const int*)d_in[2];
    const float* W1  = (const float*)d_in[3];
    const float* b1  = (const float*)d_in[4];
    const float* W2  = (const float*)d_in[5];
    const float* b2  = (const float*)d_in[6];
    float*       out = (float*)d_out;

    const int n_nodes  = in_sizes[0] / D;
    const int n_edges  = in_sizes[2] / 2;
    const int n_chunks = (n_edges + CHUNK_E - 1) / CHUNK_E;

    convert_tables<<<1480, 256>>>(src, dst, n_nodes);

    cudaFuncSetAttribute(edge_decoder_tc,
                         cudaFuncAttributeMaxDynamicSharedMemorySize, SMEM_TOTAL);
    int grid = GRID < (n_chunks + 7) / 8 ? GRID : (n_chunks + 7) / 8;
    edge_decoder_tc<<<grid, NTHREADS, SMEM_TOTAL>>>(
        ei, W1, b1, W2, b2, out, n_edges, n_chunks);
}

// round 17
// speedup vs baseline: 3.0264x; 1.0258x over previous
#include <cuda_runtime.h>
#include <cuda_fp16.h>
#include <cstdint>

// EdgeDecoder: out[e] = sigmoid( relu([src_e ; dst_e] @ W1 + b1) @ W2 + b2 )
// Round 17: 1024 threads / 32 warps. 8 pipelines x 4 warps, warp tile 32x32
// (32 accum regs -> 64-reg cap -> occupancy 50%). Single-pass fp16 MMA,
// 32-edge chunks, double-buffered cp.async, index prefetch, named barriers.

#define D        128
#define K2       256
#define CHUNK_E  32                  // edges per group-chunk
#define NTHREADS 1024
#define GRID     148
#define N_NODES_MAX 100000

// SMEM layout (bytes)
#define OFF_W     0                  // W^T fp16 [128 n][264 k] (stride 528B) = 67584
#define OFF_X     67584              // 8 groups x 2 bufs x (32 rows x 272B)
#define XBUF_SZ   8704
#define XGRP_SZ   17408
#define OFF_B1    (OFF_X + 8 * XGRP_SZ)   // 206848
#define OFF_W2    (OFF_B1 + 512)
#define OFF_HP    (OFF_W2 + 512)     // 8 groups x f32[32][4] = 4096
#define SMEM_TOTAL (OFF_HP + 4096)   // 211968

// Pre-converted fp16 node tables: 256B/node
__device__ __align__(16) __half g_src_h[(size_t)N_NODES_MAX * 128];
__device__ __align__(16) __half g_dst_h[(size_t)N_NODES_MAX * 128];

__device__ __forceinline__ uint32_t smem_u32(const void* p) {
    uint32_t a;
    asm("{ .reg .u64 t; cvta.to.shared.u64 t, %1; cvt.u32.u64 %0, t; }" : "=r"(a) : "l"(p));
    return a;
}
__device__ __forceinline__ void cp16(uint32_t saddr, const void* gaddr) {
    asm volatile("cp.async.cg.shared.global [%0], [%1], 16;" :: "r"(saddr), "l"(gaddr));
}
#define CP_COMMIT() asm volatile("cp.async.commit_group;" ::: "memory")
#define CP_WAIT1()  asm volatile("cp.async.wait_group 1;" ::: "memory")

__device__ __forceinline__ void ldsm_x4(uint32_t* r, uint32_t addr) {
    asm volatile("ldmatrix.sync.aligned.m8n8.x4.shared.b16 {%0,%1,%2,%3}, [%4];"
                 : "=r"(r[0]), "=r"(r[1]), "=r"(r[2]), "=r"(r[3]) : "r"(addr));
}
__device__ __forceinline__ void mma16816(float c[4], const uint32_t a[4],
                                         uint32_t b0, uint32_t b1) {
    asm volatile(
        "mma.sync.aligned.m16n8k16.row.col.f32.f16.f16.f32 "
        "{%0,%1,%2,%3}, {%4,%5,%6,%7}, {%8,%9}, {%0,%1,%2,%3};\n"
        : "+f"(c[0]), "+f"(c[1]), "+f"(c[2]), "+f"(c[3])
        : "r"(a[0]), "r"(a[1]), "r"(a[2]), "r"(a[3]), "r"(b0), "r"(b1));
}

// ---------------- prepass: fp32 tables -> fp16 tables ----------------
__global__ void convert_tables(const float* __restrict__ src,
                               const float* __restrict__ dst, int n_nodes)
{
    const int per_tab = n_nodes * 32;     // float4 per table
    for (int v = blockIdx.x * blockDim.x + threadIdx.x; v < 2 * per_tab;
         v += gridDim.x * blockDim.x) {
        const float4* tab = (const float4*)(v < per_tab ? src : dst);
        __half* ot = (v < per_tab) ? g_src_h : g_dst_h;
        int u = (v < per_tab) ? v : v - per_tab;
        int node = u >> 5, q = u & 31;
        float4 x = tab[u];
        __half2* oh = (__half2*)(ot + (size_t)node * 128 + q * 4);
        oh[0] = __halves2half2(__float2half_rn(x.x), __float2half_rn(x.y));
        oh[1] = __halves2half2(__float2half_rn(x.z), __float2half_rn(x.w));
    }
}

// ---------------- main kernel ----------------
__global__ __launch_bounds__(NTHREADS, 1)
void edge_decoder_tc(const int* __restrict__ eidx,
                     const float* __restrict__ W1,
                     const float* __restrict__ b1,
                     const float* __restrict__ W2,
                     const float* __restrict__ b2,
                     float* __restrict__ out,
                     int n_edges, int n_chunks)
{
    extern __shared__ char smem[];
    const uint32_t sb = smem_u32(smem);
    const int tid  = threadIdx.x;
    const int lane = tid & 31;
    const int warp = tid >> 5;
    const int grp  = warp >> 2;           // 0..7 : independent pipeline
    const int wc   = warp & 3;            // 0..3 : 32-col slice
    const int gt   = tid & 127;           // thread id within group

    float* b1s = (float*)(smem + OFF_B1);
    float* w2s = (float*)(smem + OFF_W2);
    float* HpG = (float*)(smem + OFF_HP) + grp * 128;   // [32][4]

    const uint32_t xg = sb + OFF_X + (uint32_t)grp * XGRP_SZ;

    #define BARG() asm volatile("bar.sync %0, %1;" :: "r"(grp + 1), "r"(128) : "memory")

    // ---- gather: 4 threads per edge row (256B each row, 64B per thread) ----
    const int grow = gt >> 2;             // 0..31
    const int gc   = gt & 3;              // 64B slice

    auto ld_idx = [&](int ch, int half) -> int {
        int idx = 0;
        if (ch < n_chunks) {
            int e = ch * CHUNK_E + grow;
            if (e < n_edges) idx = eidx[(half ? n_edges : 0) + e];
        }
        return idx;
    };

    auto issue_half = [&](int ch, int half, int hb, int idx) {
        if (ch < n_chunks) {
            const char* g = (const char*)(half ? g_dst_h : g_src_h) + (size_t)idx * 256;
            uint32_t d = xg + (uint32_t)hb * XBUF_SZ + (uint32_t)grow * 272;
            #pragma unroll
            for (int i = 0; i < 4; ++i)
                cp16(d + (gc * 4 + i) * 16, g + (gc * 4 + i) * 16);
        }
        CP_COMMIT();
    };

    const int cstride = gridDim.x * 8;
    int chunk = blockIdx.x * 8 + grp;
    issue_half(chunk, 0, 0, ld_idx(chunk, 0));    // prologue: src of first chunk
    int cur_d = ld_idx(chunk, 1);                 // this chunk's dst index
    int nxt_s = ld_idx(chunk + cstride, 0);       // next chunk's src index

    // ---- one-time: W1 -> transposed fp16 (stride 528B); b1/W2 ----
    {
        __half* w = (__half*)(smem + OFF_W);
        for (int i = tid; i < K2 * D; i += NTHREADS) {
            int k = i >> 7;
            int n = i & 127;
            w[n * 264 + k] = __float2half_rn(W1[i]);
        }
        if (tid < 128) { b1s[tid] = b1[tid]; w2s[tid] = W2[tid]; }
    }
    const float b2v = b2[0];

    // ---- MMA geometry: warp tile 32 edges x 32 cols ----
    const int quad = lane >> 3, qr = lane & 7;
    const uint32_t aOff = (uint32_t)(((quad & 1) * 8 + qr) * 272 + (quad >> 1) * 16);
    const uint32_t bBase = sb + OFF_W
        + (uint32_t)((wc * 32 + (quad >> 1) * 8 + qr) * 528 + (quad & 1) * 16);

    __syncthreads();                      // W staged (one-time, CTA-wide)

    for (; chunk < n_chunks; chunk += cstride) {
        float c[2][4][4];
        #pragma unroll
        for (int mt = 0; mt < 2; ++mt)
            #pragma unroll
            for (int nt = 0; nt < 4; ++nt)
                #pragma unroll
                for (int r = 0; r < 4; ++r) c[mt][nt][r] = 0.f;

        auto mma_half = [&](int h, int hb) {
            const uint32_t aBase = xg + (uint32_t)hb * XBUF_SZ + aOff;
            const uint32_t bK    = (uint32_t)h * 256;
            #pragma unroll 4
            for (int ks = 0; ks < 8; ++ks) {
                const uint32_t ko = (uint32_t)ks * 32;
                uint32_t ah[8], bh[8];
                ldsm_x4(ah,     aBase + ko);
                ldsm_x4(ah + 4, aBase + 4352 + ko);
                ldsm_x4(bh,     bBase + bK + ko);
                ldsm_x4(bh + 4, bBase + 8448 + bK + ko);
                #pragma unroll
                for (int mt = 0; mt < 2; ++mt) {
                    #pragma unroll
                    for (int nt = 0; nt < 4; ++nt) {
                        uint32_t b0 = bh[(nt >> 1) * 4 + (nt & 1) * 2];
                        uint32_t b1r = bh[(nt >> 1) * 4 + (nt & 1) * 2 + 1];
                        mma16816(c[mt][nt], ah + mt * 4, b0, b1r);
                    }
                }
            }
        };

        issue_half(chunk, 1, 1, cur_d);   // dst half into buf1 (idx prefetched)
        CP_WAIT1();                       // buf0 (src) complete
        BARG();                           // buf0 ready group-wide

        int nxt_d = ld_idx(chunk + cstride, 1);   // hide LDG under mma(0)
        mma_half(0, 0);
        BARG();                           // buf0 reads done

        issue_half(chunk + cstride, 0, 0, nxt_s); // next src (idx prefetched)
        CP_WAIT1();                       // buf1 (dst) complete
        BARG();                           // buf1 ready group-wide

        int nxt2_s = ld_idx(chunk + 2 * cstride, 0);  // hide LDG under mma(1)
        mma_half(1, 1);

        // ---- epilogue: relu + W2 dot over this warp's 32 cols ----
        {
            const int tq = lane >> 2;
            const int tk = lane & 3;
            #pragma unroll
            for (int mt = 0; mt < 2; ++mt) {
                float s0 = 0.f, s1 = 0.f;
                #pragma unroll
                for (int nt = 0; nt < 4; ++nt) {
                    int col = wc * 32 + nt * 8 + tk * 2;
                    float ba = b1s[col], bb = b1s[col + 1];
                    float wa = w2s[col], wb = w2s[col + 1];
                    float h;
                    h = c[mt][nt][0] + ba; h = h > 0.f ? h : 0.f; s0 = fmaf(h, wa, s0);
                    h = c[mt][nt][1] + bb; h = h > 0.f ? h : 0.f; s0 = fmaf(h, wb, s0);
                    h = c[mt][nt][2] + ba; h = h > 0.f ? h : 0.f; s1 = fmaf(h, wa, s1);
                    h = c[mt][nt][3] + bb; h = h > 0.f ? h : 0.f; s1 = fmaf(h, wb, s1);
                }
                s0 += __shfl_xor_sync(0xffffffffu, s0, 1);
                s0 += __shfl_xor_sync(0xffffffffu, s0, 2);
                s1 += __shfl_xor_sync(0xffffffffu, s1, 1);
                s1 += __shfl_xor_sync(0xffffffffu, s1, 2);
                if (tk == 0) {
                    HpG[(mt * 16 + tq)     * 4 + wc] = s0;
                    HpG[(mt * 16 + tq + 8) * 4 + wc] = s1;
                }
            }
        }
        BARG();                           // Hpart ready; buf1 reads done

        if (wc == 0) {
            int e = chunk * CHUNK_E + lane;
            if (e < n_edges) {
                const float* hp = HpG + lane * 4;
                float s = (hp[0] + hp[1]) + (hp[2] + hp[3]) + b2v;
                out[e] = 1.f / (1.f + expf(-s));
            }
        }
        // next HpG write is 3 group-barriers away -> store race-free

        cur_d = nxt_d;                    // rotate prefetched indices
        nxt_s = nxt2_s;
    }
    #undef BARG
}

extern "C" void kernel_launch(void* const* d_in, const int* in_sizes, int n_in,
                              void* d_out, int out_size)
{
    const float* src = (const float*)d_in[0];
    const float* dst = (const float*)d_in[1];
    const int*   ei  = (const int*)d_in[2];
    const float* W1  = (const float*)d_in[3];
    const float* b1  = (const float*)d_in[4];
    const float* W2  = (const float*)d_in[5];
    const float* b2  = (const float*)d_in[6];
    float*       out = (float*)d_out;

    const int n_nodes  = in_sizes[0] / D;
    const int n_edges  = in_sizes[2] / 2;
    const int n_chunks = (n_edges + CHUNK_E - 1) / CHUNK_E;

    convert_tables<<<1480, 256>>>(src, dst, n_nodes);

    cudaFuncSetAttribute(edge_decoder_tc,
                         cudaFuncAttributeMaxDynamicSharedMemorySize, SMEM_TOTAL);
    int grid = GRID < (n_chunks + 7) / 8 ? GRID : (n_chunks + 7) / 8;
    edge_decoder_tc<<<grid, NTHREADS, SMEM_TOTAL>>>(
        ei, W1, b1, W2, b2, out, n_edges, n_chunks);
}